// round 5
// baseline (speedup 1.0000x reference)
#include <cuda_runtime.h>
#include <cstdint>

#define FN   128
#define FE   32
#define MSGW 32
#define QW   192          // Q cols: [0,32)=nf@We0, [32,64)=nf@We1, [64,192)=nf@Wn0
#define MAXN 50000
#define BE   256          // edges per block in k_edges

typedef unsigned long long ull;

__device__ float g_Q[(size_t)MAXN * QW];     // 38.4 MB
__device__ float g_MS[(size_t)MAXN * MSGW];  // 6.4 MB
__device__ int   g_is64;

static __device__ __forceinline__ ull pack2(float lo, float hi) {
    ull r;
    asm("mov.b64 %0, {%1,%2};" : "=l"(r) : "f"(lo), "f"(hi));
    return r;
}
static __device__ __forceinline__ void unpack2(ull v, float& lo, float& hi) {
    asm("mov.b64 {%0,%1}, %2;" : "=f"(lo), "=f"(hi) : "l"(v));
}
#define FMA2(acc, a, b) asm("fma.rn.f32x2 %0, %1, %2, %0;" : "+l"(acc) : "l"(a), "l"(b))

// ---------------------------------------------------------------------------
// Detect index dtype: int64 indices (< 50000) have zero high words.
// ---------------------------------------------------------------------------
__global__ void k_detect(const unsigned* __restrict__ wds, int E) {
    __shared__ unsigned red[128];
    int sample = min(16384, E);
    unsigned v = 0;
    for (int i = threadIdx.x; i < sample; i += 128) v |= wds[2 * i + 1];
    red[threadIdx.x] = v;
    __syncthreads();
    for (int s = 64; s > 0; s >>= 1) {
        if (threadIdx.x < s) red[threadIdx.x] |= red[threadIdx.x + s];
        __syncthreads();
    }
    if (threadIdx.x == 0) g_is64 = (red[0] == 0u) ? 1 : 0;
}

// ---------------------------------------------------------------------------
// Zero message sums (float4 stores).
// ---------------------------------------------------------------------------
__global__ void k_zero(int N) {
    int i = blockIdx.x * blockDim.x + threadIdx.x;
    int tot4 = N * MSGW / 4;
    if (i < tot4) ((float4*)g_MS)[i] = make_float4(0.f, 0.f, 0.f, 0.f);
}

// ---------------------------------------------------------------------------
// K1: Q[N,192] = nf[N,128] @ [We0 | We1 | Wn0].
// Tile 64 nodes x 192 cols, 256 threads. Thread = (pair p = t>>3, colgroup
// cg = t&7 owning 24 cols). Accumulators packed along M (node pair) in f32x2.
// Weights pre-splatted to u64 in smem, stride 26 ull per colgroup
// (13 16B-chunks, odd -> conflict-free LDS.128). A: [k][pair] u64, LDS.64
// broadcast. K chunked by 16 to stay under 48KB static smem.
// ---------------------------------------------------------------------------
__global__ __launch_bounds__(256) void k_gemm1(const float* __restrict__ nf,
                                               const float* __restrict__ We,
                                               const float* __restrict__ Wn,
                                               int N) {
    __shared__ ull sA[16 * 33];     // [k][pair], float view [k][66]
    __shared__ ull sW[16 * 208];    // [k][cg*26 + col], splatted
    float* sAf = (float*)sA;

    int t  = threadIdx.x;
    int m0 = blockIdx.x * 64;
    int p  = t >> 3;
    int cg = t & 7;

    ull acc[24];
#pragma unroll
    for (int c = 0; c < 24; c++) acc[c] = 0ULL;

    for (int kc = 0; kc < FN; kc += 16) {
        __syncthreads();
#pragma unroll
        for (int id = t; id < 64 * 16; id += 256) {
            int k = id & 15, m = id >> 4;
            int n = m0 + m;
            sAf[k * 66 + m] = (n < N) ? nf[(size_t)n * FN + kc + k] : 0.f;
        }
#pragma unroll
        for (int id = t; id < 16 * 192; id += 256) {
            int k = id / 192, c = id - k * 192;
            int kk = kc + k;
            float v;
            if (c < 32)      v = We[(size_t)kk * MSGW + c];
            else if (c < 64) v = We[(size_t)(FN + kk) * MSGW + (c - 32)];
            else             v = Wn[(size_t)kk * FN + (c - 64)];
            int wcg = c / 24, wc = c - wcg * 24;
            ((float2*)sW)[k * 208 + wcg * 26 + wc] = make_float2(v, v);
        }
        __syncthreads();

#pragma unroll
        for (int k = 0; k < 16; k++) {
            ull a = sA[k * 33 + p];
            const ulonglong2* wp = (const ulonglong2*)&sW[k * 208 + cg * 26];
#pragma unroll
            for (int i = 0; i < 12; i++) {
                ulonglong2 w = wp[i];
                FMA2(acc[2 * i],     a, w.x);
                FMA2(acc[2 * i + 1], a, w.y);
            }
        }
    }

    int nlo = m0 + 2 * p;
    float flo[24], fhi[24];
#pragma unroll
    for (int c = 0; c < 24; c++) unpack2(acc[c], flo[c], fhi[c]);
    if (nlo < N) {
        float* q = &g_Q[(size_t)nlo * QW + cg * 24];
#pragma unroll
        for (int v = 0; v < 6; v++)
            *(float4*)&q[4 * v] = make_float4(flo[4 * v], flo[4 * v + 1],
                                              flo[4 * v + 2], flo[4 * v + 3]);
    }
    if (nlo + 1 < N) {
        float* q = &g_Q[(size_t)(nlo + 1) * QW + cg * 24];
#pragma unroll
        for (int v = 0; v < 6; v++)
            *(float4*)&q[4 * v] = make_float4(fhi[4 * v], fhi[4 * v + 1],
                                              fhi[4 * v + 2], fhi[4 * v + 3]);
    }
}

// ---------------------------------------------------------------------------
// K2: 256 edges/block, thread-owns-edge.
//  A: stage ef rows in smem (conflict-free), pull own row to 32 regs,
//     GEMM vs broadcast We2 (cols packed in f32x2), write msg back to smem.
//  B: 8 lanes/edge float4: msg + Q[n0,0:32] + Q[n1,32:64] + be, relu,
//     red.global.add.v4.f32 into g_MS[n0].
// ---------------------------------------------------------------------------
__global__ __launch_bounds__(256) void k_edges(const void* __restrict__ idx,
                                               const float* __restrict__ ef,
                                               const float* __restrict__ We,
                                               const float* __restrict__ be,
                                               int E) {
    __shared__ float sBuf[BE * 36];   // ef rows, then reused for msg
    __shared__ float sW2[32 * 32];    // We2 [k][c] contiguous (uniform loads)
    __shared__ int   sN0[BE], sN1[BE];
    __shared__ float sBe[32];

    int t  = threadIdx.x;
    int e0 = blockIdx.x * BE;
    int is64 = g_is64;

    {
        int e = e0 + t;
        if (e < E) {
            if (is64) {
                const long long* pp = (const long long*)idx;
                sN0[t] = (int)pp[e];
                sN1[t] = (int)pp[(size_t)E + e];
            } else {
                const int* pp = (const int*)idx;
                sN0[t] = pp[e];
                sN1[t] = pp[(size_t)E + e];
            }
        } else { sN0[t] = -1; sN1[t] = 0; }
    }
#pragma unroll
    for (int id = t; id < 32 * 32; id += 256) {
        int k = id >> 5, c = id & 31;
        sW2[k * 32 + c] = We[(size_t)(2 * FN + k) * MSGW + c];
    }
    if (t < 32) sBe[t] = be[t];
#pragma unroll
    for (int id = t; id < BE * 8; id += 256) {
        int el = id >> 3, j = id & 7;
        int e = e0 + el;
        float4 v = (e < E) ? ((const float4*)ef)[(size_t)e * 8 + j]
                           : make_float4(0.f, 0.f, 0.f, 0.f);
        *(float4*)&sBuf[el * 36 + 4 * j] = v;
    }
    __syncthreads();

    // pull own row (stride 36 floats -> conflict-free LDS.128 phases)
    float efr[32];
#pragma unroll
    for (int j = 0; j < 8; j++) {
        float4 v = *(const float4*)&sBuf[t * 36 + 4 * j];
        efr[4 * j] = v.x; efr[4 * j + 1] = v.y;
        efr[4 * j + 2] = v.z; efr[4 * j + 3] = v.w;
    }
    __syncthreads();   // all reads done before sBuf is overwritten

    // acc[j] holds msg cols {2j, 2j+1}
    ull acc[16];
#pragma unroll
    for (int i = 0; i < 16; i++) acc[i] = 0ULL;
#pragma unroll
    for (int k = 0; k < 32; k++) {
        ull ek = pack2(efr[k], efr[k]);
        const ulonglong2* wp = (const ulonglong2*)&sW2[k * 32];  // uniform
#pragma unroll
        for (int i = 0; i < 8; i++) {
            ulonglong2 w = wp[i];             // cols 4i..4i+3
            FMA2(acc[2 * i],     ek, w.x);
            FMA2(acc[2 * i + 1], ek, w.y);
        }
    }
    // msg -> smem: ALL 32 cols (8 x ulonglong2 = 8 x 4 floats), col-correct
#pragma unroll
    for (int i = 0; i < 8; i++) {
        ulonglong2 v;
        v.x = acc[2 * i];       // cols 4i, 4i+1
        v.y = acc[2 * i + 1];   // cols 4i+2, 4i+3
        *(ulonglong2*)&sBuf[t * 36 + 4 * i] = v;
    }
    __syncthreads();

    // Phase B
    int sub = t & 7;
#pragma unroll
    for (int pass = 0; pass < 8; pass++) {
        int m  = pass * 32 + (t >> 3);
        int n0 = sN0[m];
        if (n0 >= 0) {
            int n1 = sN1[m];
            float4 mv = *(const float4*)&sBuf[m * 36 + sub * 4];
            float4 q0 = ((const float4*)&g_Q[(size_t)n0 * QW])[sub];
            float4 q1 = ((const float4*)&g_Q[(size_t)n1 * QW + 32])[sub];
            float4 bv = *(const float4*)&sBe[sub * 4];
            float x0 = fmaxf(mv.x + q0.x + q1.x + bv.x, 0.f);
            float x1 = fmaxf(mv.y + q0.y + q1.y + bv.y, 0.f);
            float x2 = fmaxf(mv.z + q0.z + q1.z + bv.z, 0.f);
            float x3 = fmaxf(mv.w + q0.w + q1.w + bv.w, 0.f);
            float* dst = &g_MS[(size_t)n0 * MSGW + sub * 4];
            asm volatile("red.global.add.v4.f32 [%0], {%1,%2,%3,%4};"
                         :: "l"(dst), "f"(x0), "f"(x1), "f"(x2), "f"(x3)
                         : "memory");
        }
    }
}

// ---------------------------------------------------------------------------
// K3: out[N,128] = relu(Q[:,64:192] + MS @ Wn1 + bn).
// Tile 64 nodes x 128 cols, 256 threads: pair p = t>>3, cg = t&7 (16 cols).
// Wn1 splatted u64, cg stride 18 ull (9 chunks, odd -> conflict-free).
// ---------------------------------------------------------------------------
__global__ __launch_bounds__(256) void k_nodes(const float* __restrict__ Wn,
                                               const float* __restrict__ bn,
                                               float* __restrict__ out,
                                               int N) {
    __shared__ ull sMS[32 * 33];     // [k][pair], float view [k][66]
    __shared__ ull sWn[32 * 144];    // [k][cg*18 + col], splatted
    __shared__ float sBn[128];
    float* sMSf = (float*)sMS;

    int t  = threadIdx.x;
    int m0 = blockIdx.x * 64;
    int p  = t >> 3;
    int cg = t & 7;

#pragma unroll
    for (int id = t; id < 32 * 128; id += 256) {
        int k = id >> 7, c = id & 127;
        float v = Wn[(size_t)(FN + k) * FN + c];
        int wcg = c >> 4, wc = c & 15;
        ((float2*)sWn)[k * 144 + wcg * 18 + wc] = make_float2(v, v);
    }
#pragma unroll
    for (int id = t; id < 64 * 32; id += 256) {
        int k = id & 31, m = id >> 5;
        int n = m0 + m;
        sMSf[k * 66 + m] = (n < N) ? g_MS[(size_t)n * MSGW + k] : 0.f;
    }
    if (t < 128) sBn[t] = bn[t];
    __syncthreads();

    ull acc[16];
#pragma unroll
    for (int i = 0; i < 16; i++) acc[i] = 0ULL;
#pragma unroll
    for (int k = 0; k < 32; k++) {
        ull a = sMS[k * 33 + p];
        const ulonglong2* wp = (const ulonglong2*)&sWn[k * 144 + cg * 18];
#pragma unroll
        for (int i = 0; i < 8; i++) {
            ulonglong2 w = wp[i];
            FMA2(acc[2 * i],     a, w.x);
            FMA2(acc[2 * i + 1], a, w.y);
        }
    }

    int nlo = m0 + 2 * p;
    float flo[16], fhi[16];
#pragma unroll
    for (int c = 0; c < 16; c++) unpack2(acc[c], flo[c], fhi[c]);

#pragma unroll
    for (int half = 0; half < 2; half++) {
        int n = nlo + half;
        if (n < N) {
            const float* f = half ? fhi : flo;
            const float* qb = &g_Q[(size_t)n * QW + 64 + cg * 16];
            float* ob = &out[(size_t)n * FN + cg * 16];
#pragma unroll
            for (int v = 0; v < 4; v++) {
                float4 q = *(const float4*)&qb[4 * v];
                float4 b = *(const float4*)&sBn[cg * 16 + 4 * v];
                float4 o;
                o.x = fmaxf(f[4 * v]     + q.x + b.x, 0.f);
                o.y = fmaxf(f[4 * v + 1] + q.y + b.y, 0.f);
                o.z = fmaxf(f[4 * v + 2] + q.z + b.z, 0.f);
                o.w = fmaxf(f[4 * v + 3] + q.w + b.w, 0.f);
                *(float4*)&ob[4 * v] = o;
            }
        }
    }
}

// ---------------------------------------------------------------------------
extern "C" void kernel_launch(void* const* d_in, const int* in_sizes, int n_in,
                              void* d_out, int out_size) {
    const float* nf  = (const float*)d_in[0];
    const void*  idx = d_in[1];
    const float* ef  = (const float*)d_in[2];
    const float* We  = (const float*)d_in[3];
    const float* be  = (const float*)d_in[4];
    const float* Wn  = (const float*)d_in[5];
    const float* bn  = (const float*)d_in[6];
    float* out = (float*)d_out;

    int N = in_sizes[0] / FN;
    int E = in_sizes[2] / FE;

    k_detect<<<1, 128>>>((const unsigned*)idx, E);
    k_zero<<<(N * MSGW / 4 + 255) / 256, 256>>>(N);
    k_gemm1<<<(N + 63) / 64, 256>>>(nf, We, Wn, N);
    k_edges<<<(E + BE - 1) / BE, 256>>>(idx, ef, We, be, E);
    k_nodes<<<(N + 63) / 64, 256>>>(Wn, bn, out, N);
}

// round 6
// speedup vs baseline: 1.6910x; 1.6910x over previous
#include <cuda_runtime.h>
#include <cstdint>

#define FN   128
#define FE   32
#define MSGW 32
#define QW   192          // Q cols: [0,32)=nf@We0, [32,64)=nf@We1, [64,192)=nf@Wn0
#define MAXN 50000
#define BE   256          // edges per block in k_edges

typedef unsigned long long ull;

__device__ float g_Q[(size_t)MAXN * QW];     // 38.4 MB
__device__ float g_MS[(size_t)MAXN * MSGW];  // 6.4 MB
__device__ int   g_is64;

static __device__ __forceinline__ ull pack2(float lo, float hi) {
    ull r;
    asm("mov.b64 %0, {%1,%2};" : "=l"(r) : "f"(lo), "f"(hi));
    return r;
}
#define FMA2(acc, a, b) asm("fma.rn.f32x2 %0, %1, %2, %0;" : "+l"(acc) : "l"(a), "l"(b))

// ---------------------------------------------------------------------------
// Detect index dtype: int64 indices (< 50000) have zero high words.
// ---------------------------------------------------------------------------
__global__ void k_detect(const unsigned* __restrict__ wds, int E) {
    __shared__ unsigned red[128];
    int sample = min(16384, E);
    unsigned v = 0;
    for (int i = threadIdx.x; i < sample; i += 128) v |= wds[2 * i + 1];
    red[threadIdx.x] = v;
    __syncthreads();
    for (int s = 64; s > 0; s >>= 1) {
        if (threadIdx.x < s) red[threadIdx.x] |= red[threadIdx.x + s];
        __syncthreads();
    }
    if (threadIdx.x == 0) g_is64 = (red[0] == 0u) ? 1 : 0;
}

// ---------------------------------------------------------------------------
// Zero message sums (float4 stores).
// ---------------------------------------------------------------------------
__global__ void k_zero(int N) {
    int i = blockIdx.x * blockDim.x + threadIdx.x;
    int tot4 = N * MSGW / 4;
    if (i < tot4) ((float4*)g_MS)[i] = make_float4(0.f, 0.f, 0.f, 0.f);
}

// ---------------------------------------------------------------------------
// K1 (scalar FFMA): Q[N,192] = nf[N,128] @ [We0 | We1 | Wn0].
// Full fused W resident in dynamic smem (98KB), loaded once per block.
// Tile: 64 nodes x 192 cols. Warp rg=t>>5 owns rows rg*8..+7 (A reads are
// warp-uniform float4). Lane owns cols {lane, lane+32, ..., lane+160}
// (stride-32 -> conflict-free LDS, coalesced STG).
// ---------------------------------------------------------------------------
__global__ __launch_bounds__(256) void k_gemm1(const float* __restrict__ nf,
                                               const float* __restrict__ We,
                                               const float* __restrict__ Wn,
                                               int N) {
    extern __shared__ float sh[];
    float* sW = sh;                 // [128][192] = 24576 floats
    float* sA = sh + 128 * 192;     // [16][68]   = 1088 floats

    int t    = threadIdx.x;
    int m0   = blockIdx.x * 64;
    int rg   = t >> 5;
    int lane = t & 31;

    // ---- load full fused W once: 6144 float4 ----
    for (int iq = t; iq < 6144; iq += 256) {
        int k = iq / 48, q = iq - k * 48;
        float4 v;
        if (q < 8)        v = ((const float4*)&We[(size_t)k * MSGW])[q];
        else if (q < 16)  v = ((const float4*)&We[(size_t)(FN + k) * MSGW])[q - 8];
        else              v = ((const float4*)&Wn[(size_t)k * FN])[q - 16];
        *(float4*)&sW[k * 192 + 4 * q] = v;
    }

    float acc[8][6];
#pragma unroll
    for (int r = 0; r < 8; r++)
#pragma unroll
        for (int c = 0; c < 6; c++) acc[r][c] = 0.f;

    for (int kc = 0; kc < FN; kc += 16) {
        __syncthreads();   // protects sA reuse (and first-iter W fill)
        // stage A chunk transposed: [k][m], 1024 elems, 4 per thread
#pragma unroll
        for (int id = t; id < 16 * 64; id += 256) {
            int k = id & 15, m = id >> 4;
            int n = m0 + m;
            sA[k * 68 + m] = (n < N) ? nf[(size_t)n * FN + kc + k] : 0.f;
        }
        __syncthreads();

#pragma unroll
        for (int k = 0; k < 16; k++) {
            const float4* ap = (const float4*)&sA[k * 68 + rg * 8];  // uniform
            float4 a0 = ap[0], a1 = ap[1];
            float a[8] = {a0.x, a0.y, a0.z, a0.w, a1.x, a1.y, a1.z, a1.w};
            const float* wrow = &sW[(kc + k) * 192 + lane];
            float w[6];
#pragma unroll
            for (int c = 0; c < 6; c++) w[c] = wrow[32 * c];
#pragma unroll
            for (int r = 0; r < 8; r++)
#pragma unroll
                for (int c = 0; c < 6; c++)
                    acc[r][c] = fmaf(a[r], w[c], acc[r][c]);
        }
    }

#pragma unroll
    for (int r = 0; r < 8; r++) {
        int n = m0 + rg * 8 + r;
        if (n < N) {
            float* q = &g_Q[(size_t)n * QW + lane];
#pragma unroll
            for (int c = 0; c < 6; c++) q[32 * c] = acc[r][c];
        }
    }
}

// ---------------------------------------------------------------------------
// K2 (unchanged from R5, measured 75.5us): 256 edges/block, thread-owns-edge.
// ---------------------------------------------------------------------------
__global__ __launch_bounds__(256) void k_edges(const void* __restrict__ idx,
                                               const float* __restrict__ ef,
                                               const float* __restrict__ We,
                                               const float* __restrict__ be,
                                               int E) {
    __shared__ float sBuf[BE * 36];   // ef rows, then reused for msg
    __shared__ float sW2[32 * 32];    // We2 [k][c]
    __shared__ int   sN0[BE], sN1[BE];
    __shared__ float sBe[32];

    int t  = threadIdx.x;
    int e0 = blockIdx.x * BE;
    int is64 = g_is64;

    {
        int e = e0 + t;
        if (e < E) {
            if (is64) {
                const long long* pp = (const long long*)idx;
                sN0[t] = (int)pp[e];
                sN1[t] = (int)pp[(size_t)E + e];
            } else {
                const int* pp = (const int*)idx;
                sN0[t] = pp[e];
                sN1[t] = pp[(size_t)E + e];
            }
        } else { sN0[t] = -1; sN1[t] = 0; }
    }
#pragma unroll
    for (int id = t; id < 32 * 32; id += 256) {
        int k = id >> 5, c = id & 31;
        sW2[k * 32 + c] = We[(size_t)(2 * FN + k) * MSGW + c];
    }
    if (t < 32) sBe[t] = be[t];
#pragma unroll
    for (int id = t; id < BE * 8; id += 256) {
        int el = id >> 3, j = id & 7;
        int e = e0 + el;
        float4 v = (e < E) ? ((const float4*)ef)[(size_t)e * 8 + j]
                           : make_float4(0.f, 0.f, 0.f, 0.f);
        *(float4*)&sBuf[el * 36 + 4 * j] = v;
    }
    __syncthreads();

    float efr[32];
#pragma unroll
    for (int j = 0; j < 8; j++) {
        float4 v = *(const float4*)&sBuf[t * 36 + 4 * j];
        efr[4 * j] = v.x; efr[4 * j + 1] = v.y;
        efr[4 * j + 2] = v.z; efr[4 * j + 3] = v.w;
    }
    __syncthreads();

    ull acc[16];
#pragma unroll
    for (int i = 0; i < 16; i++) acc[i] = 0ULL;
#pragma unroll
    for (int k = 0; k < 32; k++) {
        ull ek = pack2(efr[k], efr[k]);
        const ulonglong2* wp = (const ulonglong2*)&sW2[k * 32];
#pragma unroll
        for (int i = 0; i < 8; i++) {
            ulonglong2 w = wp[i];
            FMA2(acc[2 * i],     ek, w.x);
            FMA2(acc[2 * i + 1], ek, w.y);
        }
    }
#pragma unroll
    for (int i = 0; i < 8; i++) {
        ulonglong2 v;
        v.x = acc[2 * i];
        v.y = acc[2 * i + 1];
        *(ulonglong2*)&sBuf[t * 36 + 4 * i] = v;
    }
    __syncthreads();

    int sub = t & 7;
#pragma unroll
    for (int pass = 0; pass < 8; pass++) {
        int m  = pass * 32 + (t >> 3);
        int n0 = sN0[m];
        if (n0 >= 0) {
            int n1 = sN1[m];
            float4 mv = *(const float4*)&sBuf[m * 36 + sub * 4];
            float4 q0 = ((const float4*)&g_Q[(size_t)n0 * QW])[sub];
            float4 q1 = ((const float4*)&g_Q[(size_t)n1 * QW + 32])[sub];
            float4 bv = *(const float4*)&sBe[sub * 4];
            float x0 = fmaxf(mv.x + q0.x + q1.x + bv.x, 0.f);
            float x1 = fmaxf(mv.y + q0.y + q1.y + bv.y, 0.f);
            float x2 = fmaxf(mv.z + q0.z + q1.z + bv.z, 0.f);
            float x3 = fmaxf(mv.w + q0.w + q1.w + bv.w, 0.f);
            float* dst = &g_MS[(size_t)n0 * MSGW + sub * 4];
            asm volatile("red.global.add.v4.f32 [%0], {%1,%2,%3,%4};"
                         :: "l"(dst), "f"(x0), "f"(x1), "f"(x2), "f"(x3)
                         : "memory");
        }
    }
}

// ---------------------------------------------------------------------------
// K3 (scalar, R2 version): out = relu(Q[:,64:192] + MS @ Wn1 + bn).
// One warp per node.
// ---------------------------------------------------------------------------
__global__ __launch_bounds__(256) void k_nodes(const float* __restrict__ Wn,
                                               const float* __restrict__ bn,
                                               float* __restrict__ out,
                                               int N) {
    __shared__ float sW[32 * 128];
    __shared__ float sBn[128];
    int t = threadIdx.x;
#pragma unroll
    for (int id = t; id < 32 * 128; id += 256) {
        int k = id >> 7, c = id & 127;
        sW[k * 128 + c] = Wn[(size_t)(FN + k) * FN + c];
    }
    if (t < 128) sBn[t] = bn[t];
    __syncthreads();

    int lane   = t & 31;
    int warp   = (blockIdx.x * blockDim.x + t) >> 5;
    int nwarps = (gridDim.x * blockDim.x) >> 5;

    for (int n = warp; n < N; n += nwarps) {
        float m = g_MS[(size_t)n * MSGW + lane];
        float acc[4];
#pragma unroll
        for (int c = 0; c < 4; c++)
            acc[c] = g_Q[(size_t)n * QW + 64 + lane + 32 * c];
#pragma unroll
        for (int k = 0; k < 32; k++) {
            float b = __shfl_sync(0xffffffffu, m, k);
#pragma unroll
            for (int c = 0; c < 4; c++)
                acc[c] = fmaf(b, sW[k * 128 + lane + 32 * c], acc[c]);
        }
#pragma unroll
        for (int c = 0; c < 4; c++)
            out[(size_t)n * FN + lane + 32 * c] =
                fmaxf(acc[c] + sBn[lane + 32 * c], 0.f);
    }
}

// ---------------------------------------------------------------------------
extern "C" void kernel_launch(void* const* d_in, const int* in_sizes, int n_in,
                              void* d_out, int out_size) {
    const float* nf  = (const float*)d_in[0];
    const void*  idx = d_in[1];
    const float* ef  = (const float*)d_in[2];
    const float* We  = (const float*)d_in[3];
    const float* be  = (const float*)d_in[4];
    const float* Wn  = (const float*)d_in[5];
    const float* bn  = (const float*)d_in[6];
    float* out = (float*)d_out;

    int N = in_sizes[0] / FN;
    int E = in_sizes[2] / FE;

    static int smem_set = 0;
    if (!smem_set) {
        cudaFuncSetAttribute(k_gemm1, cudaFuncAttributeMaxDynamicSharedMemorySize,
                             (128 * 192 + 16 * 68) * 4);
        smem_set = 1;
    }

    k_detect<<<1, 128>>>((const unsigned*)idx, E);
    k_zero<<<(N * MSGW / 4 + 255) / 256, 256>>>(N);
    k_gemm1<<<(N + 63) / 64, 256, (128 * 192 + 16 * 68) * 4>>>(nf, We, Wn, N);
    k_edges<<<(E + BE - 1) / BE, 256>>>(idx, ef, We, be, E);
    k_nodes<<<1184, 256>>>(Wn, bn, out, N);
}

// round 7
// speedup vs baseline: 1.8022x; 1.0657x over previous
#include <cuda_runtime.h>
#include <cstdint>

#define FN   128
#define FE   32
#define MSGW 32
#define QW   192          // Q cols: [0,32)=nf@We0, [32,64)=nf@We1, [64,192)=nf@Wn0
#define MAXN 50000
#define BE   256          // edges per block in k_edges

__device__ float g_Q[(size_t)MAXN * QW];     // 38.4 MB
__device__ float g_MS[(size_t)MAXN * MSGW];  // 6.4 MB
__device__ int   g_is64;

// ---------------------------------------------------------------------------
// Detect index dtype: int64 indices (< 50000) have zero high words.
// ---------------------------------------------------------------------------
__global__ void k_detect(const unsigned* __restrict__ wds, int E) {
    __shared__ unsigned red[128];
    int sample = min(16384, E);
    unsigned v = 0;
    for (int i = threadIdx.x; i < sample; i += 128) v |= wds[2 * i + 1];
    red[threadIdx.x] = v;
    __syncthreads();
    for (int s = 64; s > 0; s >>= 1) {
        if (threadIdx.x < s) red[threadIdx.x] |= red[threadIdx.x + s];
        __syncthreads();
    }
    if (threadIdx.x == 0) g_is64 = (red[0] == 0u) ? 1 : 0;
}

// ---------------------------------------------------------------------------
// Zero message sums (float4 stores).
// ---------------------------------------------------------------------------
__global__ void k_zero(int N) {
    int i = blockIdx.x * blockDim.x + threadIdx.x;
    int tot4 = N * MSGW / 4;
    if (i < tot4) ((float4*)g_MS)[i] = make_float4(0.f, 0.f, 0.f, 0.f);
}

// ---------------------------------------------------------------------------
// K1: Q[N,192] = nf[N,128] @ [We0 | We1 | Wn0].
// Full fused W resident in dynamic smem (~100KB), loaded once per block.
// Block tile 64 rows x 192 cols, 256 thr. Warps 2x4: warp_r = wid>>2,
// warp_c = wid&3 -> warp tile 32 rows x 48 cols. Lane: ri=lane>>3 (8 rows),
// ci=lane&7 (6 cols). Per k: 2 LDS.128 (A) + 3 LDS.64 (W) + 48 FFMA.
// ---------------------------------------------------------------------------
__global__ __launch_bounds__(256) void k_gemm1(const float* __restrict__ nf,
                                               const float* __restrict__ We,
                                               const float* __restrict__ Wn,
                                               int N) {
    extern __shared__ float sh[];
    float* sW = sh;                 // [128][192]
    float* sA = sh + 128 * 192;     // [16][68]

    int t  = threadIdx.x;
    int m0 = blockIdx.x * 64;
    int wid = t >> 5, lane = t & 31;
    int warp_r = wid >> 2, warp_c = wid & 3;
    int ri = lane >> 3, ci = lane & 7;

    int rbase = warp_r * 32 + ri * 8;          // 0..56
    int cbase = warp_c * 48 + ci * 6;          // 0..186

    // ---- load full fused W once: 6144 float4 ----
    for (int iq = t; iq < 6144; iq += 256) {
        int k = iq / 48, q = iq - k * 48;
        float4 v;
        if (q < 8)        v = ((const float4*)&We[(size_t)k * MSGW])[q];
        else if (q < 16)  v = ((const float4*)&We[(size_t)(FN + k) * MSGW])[q - 8];
        else              v = ((const float4*)&Wn[(size_t)k * FN])[q - 16];
        *(float4*)&sW[k * 192 + 4 * q] = v;
    }

    float acc[8][6];
#pragma unroll
    for (int r = 0; r < 8; r++)
#pragma unroll
        for (int c = 0; c < 6; c++) acc[r][c] = 0.f;

    for (int kc = 0; kc < FN; kc += 16) {
        __syncthreads();
#pragma unroll
        for (int id = t; id < 16 * 64; id += 256) {
            int k = id & 15, m = id >> 4;
            int n = m0 + m;
            sA[k * 68 + m] = (n < N) ? nf[(size_t)n * FN + kc + k] : 0.f;
        }
        __syncthreads();

#pragma unroll
        for (int k = 0; k < 16; k++) {
            const float4* ap = (const float4*)&sA[k * 68 + rbase];
            float4 a0 = ap[0], a1 = ap[1];
            float a[8] = {a0.x, a0.y, a0.z, a0.w, a1.x, a1.y, a1.z, a1.w};
            const float2* wp = (const float2*)&sW[(kc + k) * 192 + cbase];
            float2 w01 = wp[0], w23 = wp[1], w45 = wp[2];
            float w[6] = {w01.x, w01.y, w23.x, w23.y, w45.x, w45.y};
#pragma unroll
            for (int r = 0; r < 8; r++)
#pragma unroll
                for (int c = 0; c < 6; c++)
                    acc[r][c] = fmaf(a[r], w[c], acc[r][c]);
        }
    }

#pragma unroll
    for (int r = 0; r < 8; r++) {
        int n = m0 + rbase + r;
        if (n < N) {
            float* q = &g_Q[(size_t)n * QW + cbase];
            *(float2*)&q[0] = make_float2(acc[r][0], acc[r][1]);
            *(float2*)&q[2] = make_float2(acc[r][2], acc[r][3]);
            *(float2*)&q[4] = make_float2(acc[r][4], acc[r][5]);
        }
    }
}

// ---------------------------------------------------------------------------
// K2: 256 edges/block, thread-owns-edge, scalar FFMA GEMM.
//  A: stage ef rows (stride 36, conflict-free), pull own row to 32 regs,
//     per k: 8 uniform float4 We2 loads + 32 FFMA. msg back to smem.
//  B: 8 lanes/edge float4: msg + Q[n0,0:32] + Q[n1,32:64] + be, relu,
//     red.global.add.v4.f32 into g_MS[n0].
// ---------------------------------------------------------------------------
__global__ __launch_bounds__(256) void k_edges(const void* __restrict__ idx,
                                               const float* __restrict__ ef,
                                               const float* __restrict__ We,
                                               const float* __restrict__ be,
                                               int E) {
    __shared__ float sBuf[BE * 36];   // ef rows, then reused for msg
    __shared__ float sW2[32 * 32];    // We2 [k][c]
    __shared__ int   sN0[BE], sN1[BE];
    __shared__ float sBe[32];

    int t  = threadIdx.x;
    int e0 = blockIdx.x * BE;
    int is64 = g_is64;

    {
        int e = e0 + t;
        if (e < E) {
            if (is64) {
                const long long* pp = (const long long*)idx;
                sN0[t] = (int)pp[e];
                sN1[t] = (int)pp[(size_t)E + e];
            } else {
                const int* pp = (const int*)idx;
                sN0[t] = pp[e];
                sN1[t] = pp[(size_t)E + e];
            }
        } else { sN0[t] = -1; sN1[t] = 0; }
    }
#pragma unroll
    for (int id = t; id < 32 * 32; id += 256) {
        int k = id >> 5, c = id & 31;
        sW2[k * 32 + c] = We[(size_t)(2 * FN + k) * MSGW + c];
    }
    if (t < 32) sBe[t] = be[t];
#pragma unroll
    for (int id = t; id < BE * 8; id += 256) {
        int el = id >> 3, j = id & 7;
        int e = e0 + el;
        float4 v = (e < E) ? ((const float4*)ef)[(size_t)e * 8 + j]
                           : make_float4(0.f, 0.f, 0.f, 0.f);
        *(float4*)&sBuf[el * 36 + 4 * j] = v;
    }
    __syncthreads();

    float efr[32];
#pragma unroll
    for (int j = 0; j < 8; j++) {
        float4 v = *(const float4*)&sBuf[t * 36 + 4 * j];
        efr[4 * j] = v.x; efr[4 * j + 1] = v.y;
        efr[4 * j + 2] = v.z; efr[4 * j + 3] = v.w;
    }
    __syncthreads();

    float acc[32];
#pragma unroll
    for (int i = 0; i < 32; i++) acc[i] = 0.f;
#pragma unroll
    for (int k = 0; k < 32; k++) {
        float ek = efr[k];
        const float4* wp = (const float4*)&sW2[k * 32];  // uniform
#pragma unroll
        for (int i = 0; i < 8; i++) {
            float4 w = wp[i];
            acc[4 * i]     = fmaf(ek, w.x, acc[4 * i]);
            acc[4 * i + 1] = fmaf(ek, w.y, acc[4 * i + 1]);
            acc[4 * i + 2] = fmaf(ek, w.z, acc[4 * i + 2]);
            acc[4 * i + 3] = fmaf(ek, w.w, acc[4 * i + 3]);
        }
    }
#pragma unroll
    for (int i = 0; i < 8; i++)
        *(float4*)&sBuf[t * 36 + 4 * i] =
            make_float4(acc[4 * i], acc[4 * i + 1], acc[4 * i + 2], acc[4 * i + 3]);
    __syncthreads();

    int sub = t & 7;
#pragma unroll
    for (int pass = 0; pass < 8; pass++) {
        int m  = pass * 32 + (t >> 3);
        int n0 = sN0[m];
        if (n0 >= 0) {
            int n1 = sN1[m];
            float4 mv = *(const float4*)&sBuf[m * 36 + sub * 4];
            float4 q0 = ((const float4*)&g_Q[(size_t)n0 * QW])[sub];
            float4 q1 = ((const float4*)&g_Q[(size_t)n1 * QW + 32])[sub];
            float4 bv = *(const float4*)&sBe[sub * 4];
            float x0 = fmaxf(mv.x + q0.x + q1.x + bv.x, 0.f);
            float x1 = fmaxf(mv.y + q0.y + q1.y + bv.y, 0.f);
            float x2 = fmaxf(mv.z + q0.z + q1.z + bv.z, 0.f);
            float x3 = fmaxf(mv.w + q0.w + q1.w + bv.w, 0.f);
            float* dst = &g_MS[(size_t)n0 * MSGW + sub * 4];
            asm volatile("red.global.add.v4.f32 [%0], {%1,%2,%3,%4};"
                         :: "l"(dst), "f"(x0), "f"(x1), "f"(x2), "f"(x3)
                         : "memory");
        }
    }
}

// ---------------------------------------------------------------------------
// K3: out[N,128] = relu(Q[:,64:192] + MS @ Wn1 + bn).
// Block tile 64 nodes x 128 cols, 256 thr. Warps 2x4 (32 rows x 32 cols),
// lane: ri=lane>>3 (8 rows), ci=lane&7 (4 cols). Per k: 3 LDS + 32 FFMA.
// ---------------------------------------------------------------------------
__global__ __launch_bounds__(256) void k_nodes(const float* __restrict__ Wn,
                                               const float* __restrict__ bn,
                                               float* __restrict__ out,
                                               int N) {
    __shared__ float sMS[32 * 68];    // [k][m]
    __shared__ float sWn[32 * 128];   // Wn1 [k][c]
    __shared__ float sBn[128];

    int t  = threadIdx.x;
    int m0 = blockIdx.x * 64;
    int wid = t >> 5, lane = t & 31;
    int warp_r = wid >> 2, warp_c = wid & 3;
    int ri = lane >> 3, ci = lane & 7;
    int rbase = warp_r * 32 + ri * 8;
    int cbase = warp_c * 32 + ci * 4;

#pragma unroll
    for (int id = t; id < 32 * 128; id += 256) {
        int k = id >> 7, c = id & 127;
        sWn[k * 128 + c] = Wn[(size_t)(FN + k) * FN + c];
    }
#pragma unroll
    for (int id = t; id < 64 * 32; id += 256) {
        int k = id & 31, m = id >> 5;
        int n = m0 + m;
        sMS[k * 68 + m] = (n < N) ? g_MS[(size_t)n * MSGW + k] : 0.f;
    }
    if (t < 128) sBn[t] = bn[t];
    __syncthreads();

    float acc[8][4];
#pragma unroll
    for (int r = 0; r < 8; r++)
#pragma unroll
        for (int c = 0; c < 4; c++) acc[r][c] = 0.f;

#pragma unroll
    for (int k = 0; k < 32; k++) {
        const float4* ap = (const float4*)&sMS[k * 68 + rbase];
        float4 a0 = ap[0], a1 = ap[1];
        float a[8] = {a0.x, a0.y, a0.z, a0.w, a1.x, a1.y, a1.z, a1.w};
        float4 w = *(const float4*)&sWn[k * 128 + cbase];
#pragma unroll
        for (int r = 0; r < 8; r++) {
            acc[r][0] = fmaf(a[r], w.x, acc[r][0]);
            acc[r][1] = fmaf(a[r], w.y, acc[r][1]);
            acc[r][2] = fmaf(a[r], w.z, acc[r][2]);
            acc[r][3] = fmaf(a[r], w.w, acc[r][3]);
        }
    }

    float4 b = *(const float4*)&sBn[cbase];
#pragma unroll
    for (int r = 0; r < 8; r++) {
        int n = m0 + rbase + r;
        if (n < N) {
            float4 q = *(const float4*)&g_Q[(size_t)n * QW + 64 + cbase];
            float4 o;
            o.x = fmaxf(acc[r][0] + q.x + b.x, 0.f);
            o.y = fmaxf(acc[r][1] + q.y + b.y, 0.f);
            o.z = fmaxf(acc[r][2] + q.z + b.z, 0.f);
            o.w = fmaxf(acc[r][3] + q.w + b.w, 0.f);
            *(float4*)&out[(size_t)n * FN + cbase] = o;
        }
    }
}

// ---------------------------------------------------------------------------
extern "C" void kernel_launch(void* const* d_in, const int* in_sizes, int n_in,
                              void* d_out, int out_size) {
    const float* nf  = (const float*)d_in[0];
    const void*  idx = d_in[1];
    const float* ef  = (const float*)d_in[2];
    const float* We  = (const float*)d_in[3];
    const float* be  = (const float*)d_in[4];
    const float* Wn  = (const float*)d_in[5];
    const float* bn  = (const float*)d_in[6];
    float* out = (float*)d_out;

    int N = in_sizes[0] / FN;
    int E = in_sizes[2] / FE;

    static int smem_set = 0;
    if (!smem_set) {
        cudaFuncSetAttribute(k_gemm1, cudaFuncAttributeMaxDynamicSharedMemorySize,
                             (128 * 192 + 16 * 68) * 4);
        smem_set = 1;
    }

    k_detect<<<1, 128>>>((const unsigned*)idx, E);
    k_zero<<<(N * MSGW / 4 + 255) / 256, 256>>>(N);
    k_gemm1<<<(N + 63) / 64, 256, (128 * 192 + 16 * 68) * 4>>>(nf, We, Wn, N);
    k_edges<<<(E + BE - 1) / BE, 256>>>(idx, ef, We, be, E);
    k_nodes<<<(N + 63) / 64, 256>>>(Wn, bn, out, N);
}

// round 8
// speedup vs baseline: 1.9480x; 1.0809x over previous
#include <cuda_runtime.h>
#include <cstdint>

#define FN   128
#define FE   32
#define MSGW 32
#define QW   192          // Q cols: [0,32)=nf@We0, [32,64)=nf@We1, [64,192)=nf@Wn0
#define MAXN 50000
#define BE   256          // edges per block in k_edges

__device__ float g_Q[(size_t)MAXN * QW];     // 38.4 MB
__device__ float g_MS[(size_t)MAXN * MSGW];  // 6.4 MB
__device__ int   g_is64;

// ---------------------------------------------------------------------------
// Prep: block 0 detects index dtype (int64 -> zero high words); all other
// blocks zero g_MS with float4 stores.
// ---------------------------------------------------------------------------
__global__ void k_prep(const unsigned* __restrict__ wds, int E, int N) {
    if (blockIdx.x == 0) {
        __shared__ unsigned red[256];
        int sample = min(16384, E);
        unsigned v = 0;
        for (int i = threadIdx.x; i < sample; i += 256) v |= wds[2 * i + 1];
        red[threadIdx.x] = v;
        __syncthreads();
        for (int s = 128; s > 0; s >>= 1) {
            if (threadIdx.x < s) red[threadIdx.x] |= red[threadIdx.x + s];
            __syncthreads();
        }
        if (threadIdx.x == 0) g_is64 = (red[0] == 0u) ? 1 : 0;
    } else {
        int i = (blockIdx.x - 1) * blockDim.x + threadIdx.x;
        int tot4 = N * MSGW / 4;
        if (i < tot4) ((float4*)g_MS)[i] = make_float4(0.f, 0.f, 0.f, 0.f);
    }
}

// ---------------------------------------------------------------------------
// K1: Q[N,192] = nf[N,128] @ [We0 | We1 | Wn0].
// Full fused W resident in dynamic smem (~100KB), loaded once per block.
// Block tile 64 rows x 192 cols, 256 thr. Warp tile 32x48, thread 8x6.
// ---------------------------------------------------------------------------
__global__ __launch_bounds__(256) void k_gemm1(const float* __restrict__ nf,
                                               const float* __restrict__ We,
                                               const float* __restrict__ Wn,
                                               int N) {
    extern __shared__ float sh[];
    float* sW = sh;                 // [128][192]
    float* sA = sh + 128 * 192;     // [16][68]

    int t  = threadIdx.x;
    int m0 = blockIdx.x * 64;
    int wid = t >> 5, lane = t & 31;
    int warp_r = wid >> 2, warp_c = wid & 3;
    int ri = lane >> 3, ci = lane & 7;

    int rbase = warp_r * 32 + ri * 8;          // 0..56
    int cbase = warp_c * 48 + ci * 6;          // 0..186

    for (int iq = t; iq < 6144; iq += 256) {
        int k = iq / 48, q = iq - k * 48;
        float4 v;
        if (q < 8)        v = ((const float4*)&We[(size_t)k * MSGW])[q];
        else if (q < 16)  v = ((const float4*)&We[(size_t)(FN + k) * MSGW])[q - 8];
        else              v = ((const float4*)&Wn[(size_t)k * FN])[q - 16];
        *(float4*)&sW[k * 192 + 4 * q] = v;
    }

    float acc[8][6];
#pragma unroll
    for (int r = 0; r < 8; r++)
#pragma unroll
        for (int c = 0; c < 6; c++) acc[r][c] = 0.f;

    for (int kc = 0; kc < FN; kc += 16) {
        __syncthreads();
#pragma unroll
        for (int id = t; id < 16 * 64; id += 256) {
            int k = id & 15, m = id >> 4;
            int n = m0 + m;
            sA[k * 68 + m] = (n < N) ? nf[(size_t)n * FN + kc + k] : 0.f;
        }
        __syncthreads();

#pragma unroll
        for (int k = 0; k < 16; k++) {
            const float4* ap = (const float4*)&sA[k * 68 + rbase];
            float4 a0 = ap[0], a1 = ap[1];
            float a[8] = {a0.x, a0.y, a0.z, a0.w, a1.x, a1.y, a1.z, a1.w};
            const float2* wp = (const float2*)&sW[(kc + k) * 192 + cbase];
            float2 w01 = wp[0], w23 = wp[1], w45 = wp[2];
            float w[6] = {w01.x, w01.y, w23.x, w23.y, w45.x, w45.y};
#pragma unroll
            for (int r = 0; r < 8; r++)
#pragma unroll
                for (int c = 0; c < 6; c++)
                    acc[r][c] = fmaf(a[r], w[c], acc[r][c]);
        }
    }

#pragma unroll
    for (int r = 0; r < 8; r++) {
        int n = m0 + rbase + r;
        if (n < N) {
            float* q = &g_Q[(size_t)n * QW + cbase];
            *(float2*)&q[0] = make_float2(acc[r][0], acc[r][1]);
            *(float2*)&q[2] = make_float2(acc[r][2], acc[r][3]);
            *(float2*)&q[4] = make_float2(acc[r][4], acc[r][5]);
        }
    }
}

// ---------------------------------------------------------------------------
// K2: 256 edges/block, thread-owns-edge, ef kept in smem (stride 33:
// bank = (t+k)%32, conflict-free per-k scalar reads). acc[32] in regs.
// Phase B: 8 lanes/edge float4 gather of Q + red.global.add.v4.f32.
// ---------------------------------------------------------------------------
__global__ __launch_bounds__(256, 4) void k_edges(const void* __restrict__ idx,
                                                  const float* __restrict__ ef,
                                                  const float* __restrict__ We,
                                                  const float* __restrict__ be,
                                                  int E) {
    __shared__ float sBuf[BE * 36];   // ef (stride 33), later msg (stride 36)
    __shared__ float sW2[32 * 32];    // We2 [k][c]
    __shared__ int   sN0[BE], sN1[BE];
    __shared__ float sBe[32];

    int t  = threadIdx.x;
    int e0 = blockIdx.x * BE;
    int is64 = g_is64;

    {
        int e = e0 + t;
        if (e < E) {
            if (is64) {
                const long long* pp = (const long long*)idx;
                sN0[t] = (int)pp[e];
                sN1[t] = (int)pp[(size_t)E + e];
            } else {
                const int* pp = (const int*)idx;
                sN0[t] = pp[e];
                sN1[t] = pp[(size_t)E + e];
            }
        } else { sN0[t] = -1; sN1[t] = 0; }
    }
#pragma unroll
    for (int id = t; id < 32 * 32; id += 256) {
        int k = id >> 5, c = id & 31;
        sW2[k * 32 + c] = We[(size_t)(2 * FN + k) * MSGW + c];
    }
    if (t < 32) sBe[t] = be[t];
    // ef fill: coalesced LDG.32, conflict-free STS (stride-1 within warp)
#pragma unroll
    for (int id = t; id < BE * 32; id += 256) {
        int e = e0 + (id >> 5), k = id & 31;
        float v = ((size_t)e < (size_t)E) ? ef[(size_t)e * FE + k] : 0.f;
        sBuf[(id >> 5) * 33 + k] = v;
    }
    __syncthreads();

    float acc[32];
#pragma unroll
    for (int i = 0; i < 32; i++) acc[i] = 0.f;
#pragma unroll
    for (int k = 0; k < 32; k++) {
        float ek = sW2 == nullptr ? 0.f : sBuf[t * 33 + k];  // (never null; keeps order)
        const float4* wp = (const float4*)&sW2[k * 32];      // uniform loads
#pragma unroll
        for (int i = 0; i < 8; i++) {
            float4 w = wp[i];
            acc[4 * i]     = fmaf(ek, w.x, acc[4 * i]);
            acc[4 * i + 1] = fmaf(ek, w.y, acc[4 * i + 1]);
            acc[4 * i + 2] = fmaf(ek, w.z, acc[4 * i + 2]);
            acc[4 * i + 3] = fmaf(ek, w.w, acc[4 * i + 3]);
        }
    }
    __syncthreads();   // all ef reads complete before msg overwrites sBuf

#pragma unroll
    for (int i = 0; i < 8; i++)
        *(float4*)&sBuf[t * 36 + 4 * i] =
            make_float4(acc[4 * i], acc[4 * i + 1], acc[4 * i + 2], acc[4 * i + 3]);
    __syncthreads();

    int sub = t & 7;
#pragma unroll
    for (int pass = 0; pass < 8; pass++) {
        int m  = pass * 32 + (t >> 3);
        int n0 = sN0[m];
        if (n0 >= 0) {
            int n1 = sN1[m];
            float4 mv = *(const float4*)&sBuf[m * 36 + sub * 4];
            float4 q0 = ((const float4*)&g_Q[(size_t)n0 * QW])[sub];
            float4 q1 = ((const float4*)&g_Q[(size_t)n1 * QW + 32])[sub];
            float4 bv = *(const float4*)&sBe[sub * 4];
            float x0 = fmaxf(mv.x + q0.x + q1.x + bv.x, 0.f);
            float x1 = fmaxf(mv.y + q0.y + q1.y + bv.y, 0.f);
            float x2 = fmaxf(mv.z + q0.z + q1.z + bv.z, 0.f);
            float x3 = fmaxf(mv.w + q0.w + q1.w + bv.w, 0.f);
            float* dst = &g_MS[(size_t)n0 * MSGW + sub * 4];
            asm volatile("red.global.add.v4.f32 [%0], {%1,%2,%3,%4};"
                         :: "l"(dst), "f"(x0), "f"(x1), "f"(x2), "f"(x3)
                         : "memory");
        }
    }
}

// ---------------------------------------------------------------------------
// K3: out[N,128] = relu(Q[:,64:192] + MS @ Wn1 + bn).
// Block 64 nodes x 128 cols, warp 32x32, thread 8x4.
// ---------------------------------------------------------------------------
__global__ __launch_bounds__(256) void k_nodes(const float* __restrict__ Wn,
                                               const float* __restrict__ bn,
                                               float* __restrict__ out,
                                               int N) {
    __shared__ float sMS[32 * 68];    // [k][m]
    __shared__ float sWn[32 * 128];   // Wn1 [k][c]
    __shared__ float sBn[128];

    int t  = threadIdx.x;
    int m0 = blockIdx.x * 64;
    int wid = t >> 5, lane = t & 31;
    int warp_r = wid >> 2, warp_c = wid & 3;
    int ri = lane >> 3, ci = lane & 7;
    int rbase = warp_r * 32 + ri * 8;
    int cbase = warp_c * 32 + ci * 4;

#pragma unroll
    for (int id = t; id < 32 * 128; id += 256) {
        int k = id >> 7, c = id & 127;
        sWn[k * 128 + c] = Wn[(size_t)(FN + k) * FN + c];
    }
#pragma unroll
    for (int id = t; id < 64 * 32; id += 256) {
        int k = id & 31, m = id >> 5;
        int n = m0 + m;
        sMS[k * 68 + m] = (n < N) ? g_MS[(size_t)n * MSGW + k] : 0.f;
    }
    if (t < 128) sBn[t] = bn[t];
    __syncthreads();

    float acc[8][4];
#pragma unroll
    for (int r = 0; r < 8; r++)
#pragma unroll
        for (int c = 0; c < 4; c++) acc[r][c] = 0.f;

#pragma unroll
    for (int k = 0; k < 32; k++) {
        const float4* ap = (const float4*)&sMS[k * 68 + rbase];
        float4 a0 = ap[0], a1 = ap[1];
        float a[8] = {a0.x, a0.y, a0.z, a0.w, a1.x, a1.y, a1.z, a1.w};
        float4 w = *(const float4*)&sWn[k * 128 + cbase];
#pragma unroll
        for (int r = 0; r < 8; r++) {
            acc[r][0] = fmaf(a[r], w.x, acc[r][0]);
            acc[r][1] = fmaf(a[r], w.y, acc[r][1]);
            acc[r][2] = fmaf(a[r], w.z, acc[r][2]);
            acc[r][3] = fmaf(a[r], w.w, acc[r][3]);
        }
    }

    float4 b = *(const float4*)&sBn[cbase];
#pragma unroll
    for (int r = 0; r < 8; r++) {
        int n = m0 + rbase + r;
        if (n < N) {
            float4 q = *(const float4*)&g_Q[(size_t)n * QW + 64 + cbase];
            float4 o;
            o.x = fmaxf(acc[r][0] + q.x + b.x, 0.f);
            o.y = fmaxf(acc[r][1] + q.y + b.y, 0.f);
            o.z = fmaxf(acc[r][2] + q.z + b.z, 0.f);
            o.w = fmaxf(acc[r][3] + q.w + b.w, 0.f);
            *(float4*)&out[(size_t)n * FN + cbase] = o;
        }
    }
}

// ---------------------------------------------------------------------------
extern "C" void kernel_launch(void* const* d_in, const int* in_sizes, int n_in,
                              void* d_out, int out_size) {
    const float* nf  = (const float*)d_in[0];
    const void*  idx = d_in[1];
    const float* ef  = (const float*)d_in[2];
    const float* We  = (const float*)d_in[3];
    const float* be  = (const float*)d_in[4];
    const float* Wn  = (const float*)d_in[5];
    const float* bn  = (const float*)d_in[6];
    float* out = (float*)d_out;

    int N = in_sizes[0] / FN;
    int E = in_sizes[2] / FE;

    static int smem_set = 0;
    if (!smem_set) {
        cudaFuncSetAttribute(k_gemm1, cudaFuncAttributeMaxDynamicSharedMemorySize,
                             (128 * 192 + 16 * 68) * 4);
        smem_set = 1;
    }

    int zeroBlocks = (N * MSGW / 4 + 255) / 256;
    k_prep<<<zeroBlocks + 1, 256>>>((const unsigned*)idx, E, N);
    k_gemm1<<<(N + 63) / 64, 256, (128 * 192 + 16 * 68) * 4>>>(nf, We, Wn, N);
    k_edges<<<(E + BE - 1) / BE, 256>>>(idx, ef, We, be, E);
    k_nodes<<<(N + 63) / 64, 256>>>(Wn, bn, out, N);
}

// round 9
// speedup vs baseline: 2.1309x; 1.0939x over previous
#include <cuda_runtime.h>
#include <cuda_bf16.h>
#include <cstdint>

#define FN   128
#define FE   32
#define MSGW 32
#define QW   192          // Q cols: [0,32)=nf@We0, [32,64)=nf@We1, [64,192)=nf@Wn0
#define MAXN 50000
#define BE   256          // edges per block in k_edges
#define PADA 136          // bf16 row stride for A tiles (128+8)
#define PADW 200          // bf16 row stride for W tiles (192+8)

__device__ float g_Q[(size_t)MAXN * QW];     // 38.4 MB
__device__ float g_MS[(size_t)MAXN * MSGW];  // 6.4 MB
__device__ int   g_is64;

// ---------------------------------------------------------------------------
// mma/ldmatrix helpers
// ---------------------------------------------------------------------------
static __device__ __forceinline__ uint32_t sptr(const void* p) {
    return (uint32_t)__cvta_generic_to_shared(p);
}
static __device__ __forceinline__ void ldsm_x4(uint32_t* r, uint32_t a) {
    asm volatile("ldmatrix.sync.aligned.m8n8.x4.shared.b16 {%0,%1,%2,%3},[%4];"
                 : "=r"(r[0]), "=r"(r[1]), "=r"(r[2]), "=r"(r[3]) : "r"(a));
}
static __device__ __forceinline__ void ldsm_x4t(uint32_t* r, uint32_t a) {
    asm volatile("ldmatrix.sync.aligned.m8n8.x4.trans.shared.b16 {%0,%1,%2,%3},[%4];"
                 : "=r"(r[0]), "=r"(r[1]), "=r"(r[2]), "=r"(r[3]) : "r"(a));
}
static __device__ __forceinline__ void mma16816(float* c, const uint32_t* a,
                                                uint32_t b0, uint32_t b1) {
    asm volatile(
        "mma.sync.aligned.m16n8k16.row.col.f32.bf16.bf16.f32 "
        "{%0,%1,%2,%3},{%4,%5,%6,%7},{%8,%9},{%0,%1,%2,%3};"
        : "+f"(c[0]), "+f"(c[1]), "+f"(c[2]), "+f"(c[3])
        : "r"(a[0]), "r"(a[1]), "r"(a[2]), "r"(a[3]), "r"(b0), "r"(b1));
}
static __device__ __forceinline__ __nv_bfloat162 split_hi(float2 v) {
    __nv_bfloat162 h;
    h.x = __float2bfloat16(v.x);
    h.y = __float2bfloat16(v.y);
    return h;
}
static __device__ __forceinline__ __nv_bfloat162 split_lo(float2 v, __nv_bfloat162 h) {
    __nv_bfloat162 l;
    l.x = __float2bfloat16(v.x - __bfloat162float(h.x));
    l.y = __float2bfloat16(v.y - __bfloat162float(h.y));
    return l;
}

// ---------------------------------------------------------------------------
// Prep: block 0 detects index dtype (int64 -> zero high words); all other
// blocks zero g_MS with float4 stores.
// ---------------------------------------------------------------------------
__global__ void k_prep(const unsigned* __restrict__ wds, int E, int N) {
    if (blockIdx.x == 0) {
        __shared__ unsigned red[256];
        int sample = min(16384, E);
        unsigned v = 0;
        for (int i = threadIdx.x; i < sample; i += 256) v |= wds[2 * i + 1];
        red[threadIdx.x] = v;
        __syncthreads();
        for (int s = 128; s > 0; s >>= 1) {
            if (threadIdx.x < s) red[threadIdx.x] |= red[threadIdx.x + s];
            __syncthreads();
        }
        if (threadIdx.x == 0) g_is64 = (red[0] == 0u) ? 1 : 0;
    } else {
        int i = (blockIdx.x - 1) * blockDim.x + threadIdx.x;
        int tot4 = N * MSGW / 4;
        if (i < tot4) ((float4*)g_MS)[i] = make_float4(0.f, 0.f, 0.f, 0.f);
    }
}

// ---------------------------------------------------------------------------
// K1 (tensor cores): Q[N,192] = nf @ [We0|We1|Wn0], split-bf16 (3 products).
// Block: 128 nodes x 192 cols, 512 threads. Warp (16) tile 32x48 = 2x6
// m16n8k16 tiles. A_hi/A_lo + W_hi/W_lo fully resident in 168KB smem.
// ---------------------------------------------------------------------------
__global__ __launch_bounds__(512) void k_gemm1(const float* __restrict__ nf,
                                               const float* __restrict__ We,
                                               const float* __restrict__ Wn,
                                               int N) {
    extern __shared__ __nv_bfloat16 sb[];
    __nv_bfloat16* wHi = sb;                    // [128][PADW]
    __nv_bfloat16* wLo = wHi + 128 * PADW;
    __nv_bfloat16* aHi = wLo + 128 * PADW;      // [128][PADA]
    __nv_bfloat16* aLo = aHi + 128 * PADA;

    int t  = threadIdx.x;
    int m0 = blockIdx.x * 128;

    // ---- fill W hi/lo (128 x 192, as 96 col-pairs per row) ----
    for (int id = t; id < 128 * 96; id += 512) {
        int k = id / 96, c = 2 * (id - k * 96);
        float2 v;
        if (c < 32)      v = *(const float2*)&We[(size_t)k * MSGW + c];
        else if (c < 64) v = *(const float2*)&We[(size_t)(FN + k) * MSGW + (c - 32)];
        else             v = *(const float2*)&Wn[(size_t)k * FN + (c - 64)];
        __nv_bfloat162 h = split_hi(v);
        *(__nv_bfloat162*)&wHi[k * PADW + c] = h;
        *(__nv_bfloat162*)&wLo[k * PADW + c] = split_lo(v, h);
    }
    // ---- fill A hi/lo (128 x 128, 64 col-pairs per row) ----
    for (int id = t; id < 128 * 64; id += 512) {
        int m = id >> 6, c = 2 * (id & 63);
        int n = m0 + m;
        float2 v = (n < N) ? *(const float2*)&nf[(size_t)n * FN + c]
                           : make_float2(0.f, 0.f);
        __nv_bfloat162 h = split_hi(v);
        *(__nv_bfloat162*)&aHi[m * PADA + c] = h;
        *(__nv_bfloat162*)&aLo[m * PADA + c] = split_lo(v, h);
    }
    __syncthreads();

    int wid = t >> 5, lane = t & 31;
    int warp_m = wid & 3, warp_n = wid >> 2;
    int rbase = warp_m * 32, cbase = warp_n * 48;

    // ldmatrix lane addresses (bytes)
    uint32_t aOff = (uint32_t)(((rbase + (lane & 15)) * PADA + 8 * (lane >> 4)) * 2);
    uint32_t aHiB = sptr(aHi) + aOff;
    uint32_t aLoB = sptr(aLo) + aOff;
    int brow  = (lane & 7) + 8 * ((lane >> 3) & 1);
    int bcol0 = cbase + 8 * (lane >> 4);
    uint32_t wOff = (uint32_t)((brow * PADW + bcol0) * 2);
    uint32_t wHiB = sptr(wHi) + wOff;
    uint32_t wLoB = sptr(wLo) + wOff;

    float c[2][6][4];
#pragma unroll
    for (int mt = 0; mt < 2; mt++)
#pragma unroll
        for (int nt = 0; nt < 6; nt++)
#pragma unroll
            for (int i = 0; i < 4; i++) c[mt][nt][i] = 0.f;

#pragma unroll
    for (int ks = 0; ks < 8; ks++) {
        uint32_t aoff = ks * 32;               // 16 bf16 cols
        uint32_t boff = ks * 16 * PADW * 2;    // 16 k-rows
        uint32_t ah[2][4], al[2][4], b[6][2];
        ldsm_x4(ah[0], aHiB + aoff);
        ldsm_x4(ah[1], aHiB + aoff + 16 * PADA * 2);
        ldsm_x4(al[0], aLoB + aoff);
        ldsm_x4(al[1], aLoB + aoff + 16 * PADA * 2);
#pragma unroll
        for (int j = 0; j < 3; j++) {
            uint32_t r[4];
            ldsm_x4t(r, wHiB + boff + j * 32);    // 16 n-cols = 32B
            b[2 * j][0] = r[0]; b[2 * j][1] = r[1];
            b[2 * j + 1][0] = r[2]; b[2 * j + 1][1] = r[3];
        }
#pragma unroll
        for (int mt = 0; mt < 2; mt++)
#pragma unroll
            for (int nt = 0; nt < 6; nt++) {
                mma16816(c[mt][nt], ah[mt], b[nt][0], b[nt][1]);
                mma16816(c[mt][nt], al[mt], b[nt][0], b[nt][1]);
            }
#pragma unroll
        for (int j = 0; j < 3; j++) {
            uint32_t r[4];
            ldsm_x4t(r, wLoB + boff + j * 32);
            b[2 * j][0] = r[0]; b[2 * j][1] = r[1];
            b[2 * j + 1][0] = r[2]; b[2 * j + 1][1] = r[3];
        }
#pragma unroll
        for (int mt = 0; mt < 2; mt++)
#pragma unroll
            for (int nt = 0; nt < 6; nt++)
                mma16816(c[mt][nt], ah[mt], b[nt][0], b[nt][1]);
    }

    // ---- epilogue: C frag (m16n8 f32) -> g_Q ----
    int g = lane >> 2, tg = lane & 3;
#pragma unroll
    for (int mt = 0; mt < 2; mt++)
#pragma unroll
        for (int nt = 0; nt < 6; nt++) {
            int row = m0 + rbase + 16 * mt + g;
            int col = cbase + 8 * nt + 2 * tg;
            if (row < N)
                *(float2*)&g_Q[(size_t)row * QW + col] =
                    make_float2(c[mt][nt][0], c[mt][nt][1]);
            if (row + 8 < N)
                *(float2*)&g_Q[(size_t)(row + 8) * QW + col] =
                    make_float2(c[mt][nt][2], c[mt][nt][3]);
        }
}

// ---------------------------------------------------------------------------
// K2: 256 edges/block, thread-owns-edge, ef in smem (stride 33, conflict-
// free per-k reads). Phase B: 8 lanes/edge float4 gather + red.v4.f32.
// ---------------------------------------------------------------------------
__global__ __launch_bounds__(256, 4) void k_edges(const void* __restrict__ idx,
                                                  const float* __restrict__ ef,
                                                  const float* __restrict__ We,
                                                  const float* __restrict__ be,
                                                  int E) {
    __shared__ float sBuf[BE * 36];   // ef (stride 33), later msg (stride 36)
    __shared__ float sW2[32 * 32];    // We2 [k][c]
    __shared__ int   sN0[BE], sN1[BE];
    __shared__ float sBe[32];

    int t  = threadIdx.x;
    int e0 = blockIdx.x * BE;
    int is64 = g_is64;

    {
        int e = e0 + t;
        if (e < E) {
            if (is64) {
                const long long* pp = (const long long*)idx;
                sN0[t] = (int)pp[e];
                sN1[t] = (int)pp[(size_t)E + e];
            } else {
                const int* pp = (const int*)idx;
                sN0[t] = pp[e];
                sN1[t] = pp[(size_t)E + e];
            }
        } else { sN0[t] = -1; sN1[t] = 0; }
    }
#pragma unroll
    for (int id = t; id < 32 * 32; id += 256) {
        int k = id >> 5, c = id & 31;
        sW2[k * 32 + c] = We[(size_t)(2 * FN + k) * MSGW + c];
    }
    if (t < 32) sBe[t] = be[t];
#pragma unroll
    for (int id = t; id < BE * 32; id += 256) {
        int e = e0 + (id >> 5), k = id & 31;
        float v = (e < E) ? ef[(size_t)e * FE + k] : 0.f;
        sBuf[(id >> 5) * 33 + k] = v;
    }
    __syncthreads();

    float acc[32];
#pragma unroll
    for (int i = 0; i < 32; i++) acc[i] = 0.f;
#pragma unroll
    for (int k = 0; k < 32; k++) {
        float ek = sBuf[t * 33 + k];
        const float4* wp = (const float4*)&sW2[k * 32];  // uniform loads
#pragma unroll
        for (int i = 0; i < 8; i++) {
            float4 w = wp[i];
            acc[4 * i]     = fmaf(ek, w.x, acc[4 * i]);
            acc[4 * i + 1] = fmaf(ek, w.y, acc[4 * i + 1]);
            acc[4 * i + 2] = fmaf(ek, w.z, acc[4 * i + 2]);
            acc[4 * i + 3] = fmaf(ek, w.w, acc[4 * i + 3]);
        }
    }
    __syncthreads();

#pragma unroll
    for (int i = 0; i < 8; i++)
        *(float4*)&sBuf[t * 36 + 4 * i] =
            make_float4(acc[4 * i], acc[4 * i + 1], acc[4 * i + 2], acc[4 * i + 3]);
    __syncthreads();

    int sub = t & 7;
#pragma unroll
    for (int pass = 0; pass < 8; pass++) {
        int m  = pass * 32 + (t >> 3);
        int n0 = sN0[m];
        if (n0 >= 0) {
            int n1 = sN1[m];
            float4 mv = *(const float4*)&sBuf[m * 36 + sub * 4];
            float4 q0 = ((const float4*)&g_Q[(size_t)n0 * QW])[sub];
            float4 q1 = ((const float4*)&g_Q[(size_t)n1 * QW + 32])[sub];
            float4 bv = *(const float4*)&sBe[sub * 4];
            float x0 = fmaxf(mv.x + q0.x + q1.x + bv.x, 0.f);
            float x1 = fmaxf(mv.y + q0.y + q1.y + bv.y, 0.f);
            float x2 = fmaxf(mv.z + q0.z + q1.z + bv.z, 0.f);
            float x3 = fmaxf(mv.w + q0.w + q1.w + bv.w, 0.f);
            float* dst = &g_MS[(size_t)n0 * MSGW + sub * 4];
            asm volatile("red.global.add.v4.f32 [%0], {%1,%2,%3,%4};"
                         :: "l"(dst), "f"(x0), "f"(x1), "f"(x2), "f"(x3)
                         : "memory");
        }
    }
}

// ---------------------------------------------------------------------------
// K3: out[N,128] = relu(Q[:,64:192] + MS @ Wn1 + bn).
// Block 64 nodes x 128 cols, warp 32x32, thread 8x4.
// ---------------------------------------------------------------------------
__global__ __launch_bounds__(256) void k_nodes(const float* __restrict__ Wn,
                                               const float* __restrict__ bn,
                                               float* __restrict__ out,
                                               int N) {
    __shared__ float sMS[32 * 68];    // [k][m]
    __shared__ float sWn[32 * 128];   // Wn1 [k][c]
    __shared__ float sBn[128];

    int t  = threadIdx.x;
    int m0 = blockIdx.x * 64;
    int wid = t >> 5, lane = t & 31;
    int warp_r = wid >> 2, warp_c = wid & 3;
    int ri = lane >> 3, ci = lane & 7;
    int rbase = warp_r * 32 + ri * 8;
    int cbase = warp_c * 32 + ci * 4;

#pragma unroll
    for (int id = t; id < 32 * 128; id += 256) {
        int k = id >> 7, c = id & 127;
        sWn[k * 128 + c] = Wn[(size_t)(FN + k) * FN + c];
    }
#pragma unroll
    for (int id = t; id < 64 * 32; id += 256) {
        int k = id & 31, m = id >> 5;
        int n = m0 + m;
        sMS[k * 68 + m] = (n < N) ? g_MS[(size_t)n * MSGW + k] : 0.f;
    }
    if (t < 128) sBn[t] = bn[t];
    __syncthreads();

    float acc[8][4];
#pragma unroll
    for (int r = 0; r < 8; r++)
#pragma unroll
        for (int cc = 0; cc < 4; cc++) acc[r][cc] = 0.f;

#pragma unroll
    for (int k = 0; k < 32; k++) {
        const float4* ap = (const float4*)&sMS[k * 68 + rbase];
        float4 a0 = ap[0], a1 = ap[1];
        float a[8] = {a0.x, a0.y, a0.z, a0.w, a1.x, a1.y, a1.z, a1.w};
        float4 w = *(const float4*)&sWn[k * 128 + cbase];
#pragma unroll
        for (int r = 0; r < 8; r++) {
            acc[r][0] = fmaf(a[r], w.x, acc[r][0]);
            acc[r][1] = fmaf(a[r], w.y, acc[r][1]);
            acc[r][2] = fmaf(a[r], w.z, acc[r][2]);
            acc[r][3] = fmaf(a[r], w.w, acc[r][3]);
        }
    }

    float4 b = *(const float4*)&sBn[cbase];
#pragma unroll
    for (int r = 0; r < 8; r++) {
        int n = m0 + rbase + r;
        if (n < N) {
            float4 q = *(const float4*)&g_Q[(size_t)n * QW + 64 + cbase];
            float4 o;
            o.x = fmaxf(acc[r][0] + q.x + b.x, 0.f);
            o.y = fmaxf(acc[r][1] + q.y + b.y, 0.f);
            o.z = fmaxf(acc[r][2] + q.z + b.z, 0.f);
            o.w = fmaxf(acc[r][3] + q.w + b.w, 0.f);
            *(float4*)&out[(size_t)n * FN + cbase] = o;
        }
    }
}

// ---------------------------------------------------------------------------
extern "C" void kernel_launch(void* const* d_in, const int* in_sizes, int n_in,
                              void* d_out, int out_size) {
    const float* nf  = (const float*)d_in[0];
    const void*  idx = d_in[1];
    const float* ef  = (const float*)d_in[2];
    const float* We  = (const float*)d_in[3];
    const float* be  = (const float*)d_in[4];
    const float* Wn  = (const float*)d_in[5];
    const float* bn  = (const float*)d_in[6];
    float* out = (float*)d_out;

    int N = in_sizes[0] / FN;
    int E = in_sizes[2] / FE;

    const int g1_smem = (2 * 128 * PADW + 2 * 128 * PADA) * 2;  // 172032 B
    static int smem_set = 0;
    if (!smem_set) {
        cudaFuncSetAttribute(k_gemm1, cudaFuncAttributeMaxDynamicSharedMemorySize,
                             g1_smem);
        smem_set = 1;
    }

    int zeroBlocks = (N * MSGW / 4 + 255) / 256;
    k_prep<<<zeroBlocks + 1, 256>>>((const unsigned*)idx, E, N);
    k_gemm1<<<(N + 127) / 128, 512, g1_smem>>>(nf, We, Wn, N);
    k_edges<<<(E + BE - 1) / BE, 256>>>(idx, ef, We, be, E);
    k_nodes<<<(N + 63) / 64, 256>>>(Wn, bn, out, N);
}

// round 11
// speedup vs baseline: 2.9131x; 1.3671x over previous
#include <cuda_runtime.h>
#include <cuda_bf16.h>
#include <cstdint>

#define FN   128
#define FE   32
#define MSGW 32
#define QW   192          // Q cols: [0,32)=nf@We0, [32,64)=nf@We1, [64,192)=nf@Wn0
#define MAXN 50000
#define MAXNP 50048       // padded to 64
#define BE   256

__device__ float g_Q[(size_t)MAXN * QW];
__device__ float g_MS[(size_t)MAXN * MSGW];
__device__ int   g_is64;
__device__ __nv_bfloat16 gAhi[(size_t)MAXNP * FN];
__device__ __nv_bfloat16 gAlo[(size_t)MAXNP * FN];
__device__ __nv_bfloat16 gWhi[128 * 192];
__device__ __nv_bfloat16 gWlo[128 * 192];

// ---------------------------------------------------------------------------
// helpers
// ---------------------------------------------------------------------------
static __device__ __forceinline__ uint32_t sptr(const void* p) {
    return (uint32_t)__cvta_generic_to_shared(p);
}
static __device__ __forceinline__ void ldsm_x4(uint32_t* r, uint32_t a) {
    asm volatile("ldmatrix.sync.aligned.m8n8.x4.shared.b16 {%0,%1,%2,%3},[%4];"
                 : "=r"(r[0]), "=r"(r[1]), "=r"(r[2]), "=r"(r[3]) : "r"(a));
}
static __device__ __forceinline__ void ldsm_x4t(uint32_t* r, uint32_t a) {
    asm volatile("ldmatrix.sync.aligned.m8n8.x4.trans.shared.b16 {%0,%1,%2,%3},[%4];"
                 : "=r"(r[0]), "=r"(r[1]), "=r"(r[2]), "=r"(r[3]) : "r"(a));
}
static __device__ __forceinline__ void mma16816(float* c, const uint32_t* a,
                                                uint32_t b0, uint32_t b1) {
    asm volatile(
        "mma.sync.aligned.m16n8k16.row.col.f32.bf16.bf16.f32 "
        "{%0,%1,%2,%3},{%4,%5,%6,%7},{%8,%9},{%0,%1,%2,%3};"
        : "+f"(c[0]), "+f"(c[1]), "+f"(c[2]), "+f"(c[3])
        : "r"(a[0]), "r"(a[1]), "r"(a[2]), "r"(a[3]), "r"(b0), "r"(b1));
}
#define CP16(dst, src) \
    asm volatile("cp.async.cg.shared.global [%0],[%1],16;" :: "r"(dst), "l"(src))
#define CP_COMMIT() asm volatile("cp.async.commit_group;" ::: "memory")
#define CP_WAIT(n)  asm volatile("cp.async.wait_group %0;" :: "n"(n) : "memory")

// ---------------------------------------------------------------------------
// Mega-prep: detect idx dtype, zero g_MS, split W and A into bf16 hi/lo.
// ---------------------------------------------------------------------------
__global__ void k_prep(const unsigned* __restrict__ wds,
                       const float* __restrict__ nf,
                       const float* __restrict__ We,
                       const float* __restrict__ Wn,
                       int E, int N, int zb, int wb) {
    int b = blockIdx.x, t = threadIdx.x;
    if (b == 0) {
        __shared__ unsigned red[256];
        int sample = min(16384, E);
        unsigned v = 0;
        for (int i = t; i < sample; i += 256) v |= wds[2 * i + 1];
        red[t] = v;
        __syncthreads();
        for (int s = 128; s > 0; s >>= 1) {
            if (t < s) red[t] |= red[t + s];
            __syncthreads();
        }
        if (t == 0) g_is64 = (red[0] == 0u) ? 1 : 0;
    } else if (b <= zb) {
        int i = (b - 1) * 256 + t;
        if (i < N * MSGW / 4)
            ((float4*)g_MS)[i] = make_float4(0.f, 0.f, 0.f, 0.f);
    } else if (b <= zb + wb) {
        int id = (b - 1 - zb) * 256 + t;
        if (id < 128 * 192) {
            int k = id / 192, c = id - k * 192;
            float v;
            if (c < 32)      v = We[(size_t)k * MSGW + c];
            else if (c < 64) v = We[(size_t)(FN + k) * MSGW + (c - 32)];
            else             v = Wn[(size_t)k * FN + (c - 64)];
            __nv_bfloat16 h = __float2bfloat16(v);
            gWhi[id] = h;
            gWlo[id] = __float2bfloat16(v - __bfloat162float(h));
        }
    } else {
        int id = (b - 1 - zb - wb) * 256 + t;     // float4 groups
        int row = id >> 5, q = id & 31;
        if (row < N) {
            float4 v = *(const float4*)&nf[(size_t)row * FN + 4 * q];
            __nv_bfloat162 h0, h1, l0, l1;
            h0.x = __float2bfloat16(v.x); h0.y = __float2bfloat16(v.y);
            h1.x = __float2bfloat16(v.z); h1.y = __float2bfloat16(v.w);
            l0.x = __float2bfloat16(v.x - __bfloat162float(h0.x));
            l0.y = __float2bfloat16(v.y - __bfloat162float(h0.y));
            l1.x = __float2bfloat16(v.z - __bfloat162float(h1.x));
            l1.y = __float2bfloat16(v.w - __bfloat162float(h1.y));
            size_t o = (size_t)row * FN + 4 * q;
            *(__nv_bfloat162*)&gAhi[o]     = h0;
            *(__nv_bfloat162*)&gAhi[o + 2] = h1;
            *(__nv_bfloat162*)&gAlo[o]     = l0;
            *(__nv_bfloat162*)&gAlo[o + 2] = l1;
        }
    }
}

// ---------------------------------------------------------------------------
// K1 v3: Q = nf @ [We0|We1|Wn0], split-bf16 HMMA, cp.async double-buffered.
// Block 64 rows x 192 cols, 256 thr (8 warps: warp_m=wid&1, warp_n=wid>>1).
// K chunked x4 (KC=32, 2 ksteps/chunk). Stage: AHI|ALO|WHI|WLO.
// ---------------------------------------------------------------------------
#define STG   36864
#define AHI_O 0
#define ALO_O 5120
#define WHI_O 10240
#define WLO_O 23040
#define G1_SMEM (2 * STG)

__global__ __launch_bounds__(256, 2) void k_gemm1(int N) {
    extern __shared__ char smem[];
    uint32_t sbase = sptr(smem);
    int t = threadIdx.x;
    int wid = t >> 5, lane = t & 31;
    int m0 = blockIdx.x * 64;
    int warp_m = wid & 1, warp_n = wid >> 1;
    int rbase = warp_m * 32, cbase = warp_n * 48;

    // per-thread cp.async source/dst indices
    int arow = t >> 2, aq = t & 3;          // A: 256 units (hi), same for lo
    const __nv_bfloat16* aHiS = gAhi + (size_t)(m0 + arow) * FN + aq * 8;
    const __nv_bfloat16* aLoS = gAlo + (size_t)(m0 + arow) * FN + aq * 8;
    uint32_t aHiD = sbase + AHI_O + arow * 80 + aq * 16;
    uint32_t aLoD = sbase + ALO_O + arow * 80 + aq * 16;

    // ldsm lane base offsets (bytes within stage)
    uint32_t aOff = (uint32_t)((rbase + (lane & 15)) * 80 + (lane >> 4) * 16);
    uint32_t wRow = (uint32_t)((lane & 7) + 8 * ((lane >> 3) & 1));
    uint32_t wOff = wRow * 400 + (uint32_t)(cbase + 8 * (lane >> 4)) * 2;

    float c[2][6][4];
#pragma unroll
    for (int mt = 0; mt < 2; mt++)
#pragma unroll
        for (int nt = 0; nt < 6; nt++)
#pragma unroll
            for (int i = 0; i < 4; i++) c[mt][nt][i] = 0.f;

    // ---- issue chunk 0 ----
#pragma unroll
    for (int pre = 0; pre < 1; pre++) {
        CP16(aHiD, aHiS);
        CP16(aLoD, aLoS);
#pragma unroll
        for (int j = 0; j < 3; j++) {
            int u = t + 256 * j;
            int wr = u / 24, cq = u - wr * 24;
            CP16(sbase + WHI_O + wr * 400 + cq * 16, gWhi + wr * 192 + cq * 8);
            CP16(sbase + WLO_O + wr * 400 + cq * 16, gWlo + wr * 192 + cq * 8);
        }
    }
    CP_COMMIT();

#pragma unroll
    for (int ch = 0; ch < 4; ch++) {
        uint32_t stage = (uint32_t)(ch & 1) * STG;
        if (ch < 3) {
            int kc = (ch + 1) * 32;
            uint32_t nstage = (uint32_t)((ch + 1) & 1) * STG;
            CP16(aHiD + nstage, aHiS + kc);
            CP16(aLoD + nstage, aLoS + kc);
#pragma unroll
            for (int j = 0; j < 3; j++) {
                int u = t + 256 * j;
                int wr = u / 24, cq = u - wr * 24;
                CP16(sbase + WHI_O + nstage + wr * 400 + cq * 16,
                     gWhi + (kc + wr) * 192 + cq * 8);
                CP16(sbase + WLO_O + nstage + wr * 400 + cq * 16,
                     gWlo + (kc + wr) * 192 + cq * 8);
            }
            CP_COMMIT();
            CP_WAIT(1);
        } else {
            CP_WAIT(0);
        }
        __syncthreads();   // chunk ch data visible to all warps

        uint32_t aHiB = sbase + AHI_O + stage + aOff;
        uint32_t aLoB = sbase + ALO_O + stage + aOff;
        uint32_t wHiB = sbase + WHI_O + stage + wOff;
        uint32_t wLoB = sbase + WLO_O + stage + wOff;
#pragma unroll
        for (int ks = 0; ks < 2; ks++) {
            uint32_t ah[2][4], al[2][4];
            ldsm_x4(ah[0], aHiB + ks * 32);
            ldsm_x4(ah[1], aHiB + ks * 32 + 1280);
            ldsm_x4(al[0], aLoB + ks * 32);
            ldsm_x4(al[1], aLoB + ks * 32 + 1280);
#pragma unroll
            for (int j = 0; j < 3; j++) {
                uint32_t bh[4], bl[4];
                ldsm_x4t(bh, wHiB + ks * 6400 + j * 32);
                ldsm_x4t(bl, wLoB + ks * 6400 + j * 32);
#pragma unroll
                for (int mt = 0; mt < 2; mt++) {
                    mma16816(c[mt][2 * j],     ah[mt], bh[0], bh[1]);
                    mma16816(c[mt][2 * j],     al[mt], bh[0], bh[1]);
                    mma16816(c[mt][2 * j],     ah[mt], bl[0], bl[1]);
                    mma16816(c[mt][2 * j + 1], ah[mt], bh[2], bh[3]);
                    mma16816(c[mt][2 * j + 1], al[mt], bh[2], bh[3]);
                    mma16816(c[mt][2 * j + 1], ah[mt], bl[2], bl[3]);
                }
            }
        }
        __syncthreads();   // all done reading stage before it is refilled
    }

    // ---- epilogue ----
    int g = lane >> 2, tg = lane & 3;
#pragma unroll
    for (int mt = 0; mt < 2; mt++)
#pragma unroll
        for (int nt = 0; nt < 6; nt++) {
            int row = m0 + rbase + 16 * mt + g;
            int col = cbase + 8 * nt + 2 * tg;
            if (row < N)
                *(float2*)&g_Q[(size_t)row * QW + col] =
                    make_float2(c[mt][nt][0], c[mt][nt][1]);
            if (row + 8 < N)
                *(float2*)&g_Q[(size_t)(row + 8) * QW + col] =
                    make_float2(c[mt][nt][2], c[mt][nt][3]);
        }
}

// ---------------------------------------------------------------------------
// K2: unchanged (control).
// ---------------------------------------------------------------------------
__global__ __launch_bounds__(256, 4) void k_edges(const void* __restrict__ idx,
                                                  const float* __restrict__ ef,
                                                  const float* __restrict__ We,
                                                  const float* __restrict__ be,
                                                  int E) {
    __shared__ float sBuf[BE * 36];
    __shared__ float sW2[32 * 32];
    __shared__ int   sN0[BE], sN1[BE];
    __shared__ float sBe[32];

    int t  = threadIdx.x;
    int e0 = blockIdx.x * BE;
    int is64 = g_is64;

    {
        int e = e0 + t;
        if (e < E) {
            if (is64) {
                const long long* pp = (const long long*)idx;
                sN0[t] = (int)pp[e];
                sN1[t] = (int)pp[(size_t)E + e];
            } else {
                const int* pp = (const int*)idx;
                sN0[t] = pp[e];
                sN1[t] = pp[(size_t)E + e];
            }
        } else { sN0[t] = -1; sN1[t] = 0; }
    }
#pragma unroll
    for (int id = t; id < 32 * 32; id += 256) {
        int k = id >> 5, c = id & 31;
        sW2[k * 32 + c] = We[(size_t)(2 * FN + k) * MSGW + c];
    }
    if (t < 32) sBe[t] = be[t];
#pragma unroll
    for (int id = t; id < BE * 32; id += 256) {
        int e = e0 + (id >> 5), k = id & 31;
        float v = (e < E) ? ef[(size_t)e * FE + k] : 0.f;
        sBuf[(id >> 5) * 33 + k] = v;
    }
    __syncthreads();

    float acc[32];
#pragma unroll
    for (int i = 0; i < 32; i++) acc[i] = 0.f;
#pragma unroll
    for (int k = 0; k < 32; k++) {
        float ek = sBuf[t * 33 + k];
        const float4* wp = (const float4*)&sW2[k * 32];
#pragma unroll
        for (int i = 0; i < 8; i++) {
            float4 w = wp[i];
            acc[4 * i]     = fmaf(ek, w.x, acc[4 * i]);
            acc[4 * i + 1] = fmaf(ek, w.y, acc[4 * i + 1]);
            acc[4 * i + 2] = fmaf(ek, w.z, acc[4 * i + 2]);
            acc[4 * i + 3] = fmaf(ek, w.w, acc[4 * i + 3]);
        }
    }
    __syncthreads();

#pragma unroll
    for (int i = 0; i < 8; i++)
        *(float4*)&sBuf[t * 36 + 4 * i] =
            make_float4(acc[4 * i], acc[4 * i + 1], acc[4 * i + 2], acc[4 * i + 3]);
    __syncthreads();

    int sub = t & 7;
#pragma unroll
    for (int pass = 0; pass < 8; pass++) {
        int m  = pass * 32 + (t >> 3);
        int n0 = sN0[m];
        if (n0 >= 0) {
            int n1 = sN1[m];
            float4 mv = *(const float4*)&sBuf[m * 36 + sub * 4];
            float4 q0 = ((const float4*)&g_Q[(size_t)n0 * QW])[sub];
            float4 q1 = ((const float4*)&g_Q[(size_t)n1 * QW + 32])[sub];
            float4 bv = *(const float4*)&sBe[sub * 4];
            float x0 = fmaxf(mv.x + q0.x + q1.x + bv.x, 0.f);
            float x1 = fmaxf(mv.y + q0.y + q1.y + bv.y, 0.f);
            float x2 = fmaxf(mv.z + q0.z + q1.z + bv.z, 0.f);
            float x3 = fmaxf(mv.w + q0.w + q1.w + bv.w, 0.f);
            float* dst = &g_MS[(size_t)n0 * MSGW + sub * 4];
            asm volatile("red.global.add.v4.f32 [%0], {%1,%2,%3,%4};"
                         :: "l"(dst), "f"(x0), "f"(x1), "f"(x2), "f"(x3)
                         : "memory");
        }
    }
}

// ---------------------------------------------------------------------------
// K3: unchanged (control).
// ---------------------------------------------------------------------------
__global__ __launch_bounds__(256) void k_nodes(const float* __restrict__ Wn,
                                               const float* __restrict__ bn,
                                               float* __restrict__ out,
                                               int N) {
    __shared__ float sMS[32 * 68];
    __shared__ float sWn[32 * 128];
    __shared__ float sBn[128];

    int t  = threadIdx.x;
    int m0 = blockIdx.x * 64;
    int wid = t >> 5, lane = t & 31;
    int warp_r = wid >> 2, warp_c = wid & 3;
    int ri = lane >> 3, ci = lane & 7;
    int rbase = warp_r * 32 + ri * 8;
    int cbase = warp_c * 32 + ci * 4;

#pragma unroll
    for (int id = t; id < 32 * 128; id += 256) {
        int k = id >> 7, c = id & 127;
        sWn[k * 128 + c] = Wn[(size_t)(FN + k) * FN + c];
    }
#pragma unroll
    for (int id = t; id < 64 * 32; id += 256) {
        int k = id & 31, m = id >> 5;
        int n = m0 + m;
        sMS[k * 68 + m] = (n < N) ? g_MS[(size_t)n * MSGW + k] : 0.f;
    }
    if (t < 128) sBn[t] = bn[t];
    __syncthreads();

    float acc[8][4];
#pragma unroll
    for (int r = 0; r < 8; r++)
#pragma unroll
        for (int cc = 0; cc < 4; cc++) acc[r][cc] = 0.f;

#pragma unroll
    for (int k = 0; k < 32; k++) {
        const float4* ap = (const float4*)&sMS[k * 68 + rbase];
        float4 a0 = ap[0], a1 = ap[1];
        float a[8] = {a0.x, a0.y, a0.z, a0.w, a1.x, a1.y, a1.z, a1.w};
        float4 w = *(const float4*)&sWn[k * 128 + cbase];
#pragma unroll
        for (int r = 0; r < 8; r++) {
            acc[r][0] = fmaf(a[r], w.x, acc[r][0]);
            acc[r][1] = fmaf(a[r], w.y, acc[r][1]);
            acc[r][2] = fmaf(a[r], w.z, acc[r][2]);
            acc[r][3] = fmaf(a[r], w.w, acc[r][3]);
        }
    }

    float4 b = *(const float4*)&sBn[cbase];
#pragma unroll
    for (int r = 0; r < 8; r++) {
        int n = m0 + rbase + r;
        if (n < N) {
            float4 q = *(const float4*)&g_Q[(size_t)n * QW + 64 + cbase];
            float4 o;
            o.x = fmaxf(acc[r][0] + q.x + b.x, 0.f);
            o.y = fmaxf(acc[r][1] + q.y + b.y, 0.f);
            o.z = fmaxf(acc[r][2] + q.z + b.z, 0.f);
            o.w = fmaxf(acc[r][3] + q.w + b.w, 0.f);
            *(float4*)&out[(size_t)n * FN + cbase] = o;
        }
    }
}

// ---------------------------------------------------------------------------
extern "C" void kernel_launch(void* const* d_in, const int* in_sizes, int n_in,
                              void* d_out, int out_size) {
    const float* nf  = (const float*)d_in[0];
    const void*  idx = d_in[1];
    const float* ef  = (const float*)d_in[2];
    const float* We  = (const float*)d_in[3];
    const float* be  = (const float*)d_in[4];
    const float* Wn  = (const float*)d_in[5];
    const float* bn  = (const float*)d_in[6];
    float* out = (float*)d_out;

    int N = in_sizes[0] / FN;
    int E = in_sizes[2] / FE;

    static int smem_set = 0;
    if (!smem_set) {
        cudaFuncSetAttribute(k_gemm1, cudaFuncAttributeMaxDynamicSharedMemorySize,
                             G1_SMEM);
        smem_set = 1;
    }

    int zb = (N * MSGW / 4 + 255) / 256;       // zero blocks
    int wb = (128 * 192 + 255) / 256;          // W-split blocks
    int ab = (N * 32 + 255) / 256;             // A-split blocks (float4 groups)
    k_prep<<<1 + zb + wb + ab, 256>>>((const unsigned*)idx, nf, We, Wn, E, N, zb, wb);
    k_gemm1<<<(N + 63) / 64, 256, G1_SMEM>>>(N);
    k_edges<<<(E + BE - 1) / BE, 256>>>(idx, ef, We, be, E);
    k_nodes<<<(N + 63) / 64, 256>>>(Wn, bn, out, N);
}

// round 12
// speedup vs baseline: 3.1371x; 1.0769x over previous
#include <cuda_runtime.h>
#include <cuda_bf16.h>
#include <cstdint>

#define FN   128
#define FE   32
#define MSGW 32
#define QW   192          // Q cols: [0,32)=nf@We0, [32,64)=nf@We1, [64,192)=nf@Wn0
#define MAXN 50000
#define MAXNP 50048
#define BE   256

__device__ float g_Q[(size_t)MAXN * QW];
__device__ float g_MS[(size_t)MAXN * MSGW];
__device__ int   g_is64;
__device__ __nv_bfloat16 gAhi[(size_t)MAXNP * FN];
__device__ __nv_bfloat16 gAlo[(size_t)MAXNP * FN];
__device__ __nv_bfloat16 gWhi[128 * 192];
__device__ __nv_bfloat16 gWlo[128 * 192];

// ---------------------------------------------------------------------------
// helpers
// ---------------------------------------------------------------------------
static __device__ __forceinline__ uint32_t sptr(const void* p) {
    return (uint32_t)__cvta_generic_to_shared(p);
}
static __device__ __forceinline__ void ldsm_x4(uint32_t* r, uint32_t a) {
    asm volatile("ldmatrix.sync.aligned.m8n8.x4.shared.b16 {%0,%1,%2,%3},[%4];"
                 : "=r"(r[0]), "=r"(r[1]), "=r"(r[2]), "=r"(r[3]) : "r"(a));
}
static __device__ __forceinline__ void ldsm_x4t(uint32_t* r, uint32_t a) {
    asm volatile("ldmatrix.sync.aligned.m8n8.x4.trans.shared.b16 {%0,%1,%2,%3},[%4];"
                 : "=r"(r[0]), "=r"(r[1]), "=r"(r[2]), "=r"(r[3]) : "r"(a));
}
static __device__ __forceinline__ void mma16816(float* c, const uint32_t* a,
                                                uint32_t b0, uint32_t b1) {
    asm volatile(
        "mma.sync.aligned.m16n8k16.row.col.f32.bf16.bf16.f32 "
        "{%0,%1,%2,%3},{%4,%5,%6,%7},{%8,%9},{%0,%1,%2,%3};"
        : "+f"(c[0]), "+f"(c[1]), "+f"(c[2]), "+f"(c[3])
        : "r"(a[0]), "r"(a[1]), "r"(a[2]), "r"(a[3]), "r"(b0), "r"(b1));
}
#define CP16(dst, src) \
    asm volatile("cp.async.cg.shared.global [%0],[%1],16;" :: "r"(dst), "l"(src))
#define CP_COMMIT() asm volatile("cp.async.commit_group;" ::: "memory")
#define CP_WAIT(n)  asm volatile("cp.async.wait_group %0;" :: "n"(n) : "memory")

static __device__ __forceinline__ __nv_bfloat162 bf2_hi(float a, float b) {
    __nv_bfloat162 h; h.x = __float2bfloat16(a); h.y = __float2bfloat16(b); return h;
}
static __device__ __forceinline__ __nv_bfloat162 bf2_lo(float a, float b,
                                                        __nv_bfloat162 h) {
    __nv_bfloat162 l;
    l.x = __float2bfloat16(a - __bfloat162float(h.x));
    l.y = __float2bfloat16(b - __bfloat162float(h.y));
    return l;
}

// ---------------------------------------------------------------------------
// Mega-prep: detect idx dtype, zero g_MS, split W(fused) and A into bf16 hi/lo.
// ---------------------------------------------------------------------------
__global__ void k_prep(const unsigned* __restrict__ wds,
                       const float* __restrict__ nf,
                       const float* __restrict__ We,
                       const float* __restrict__ Wn,
                       int E, int N, int zb, int wb) {
    int b = blockIdx.x, t = threadIdx.x;
    if (b == 0) {
        __shared__ unsigned red[256];
        int sample = min(16384, E);
        unsigned v = 0;
        for (int i = t; i < sample; i += 256) v |= wds[2 * i + 1];
        red[t] = v;
        __syncthreads();
        for (int s = 128; s > 0; s >>= 1) {
            if (t < s) red[t] |= red[t + s];
            __syncthreads();
        }
        if (t == 0) g_is64 = (red[0] == 0u) ? 1 : 0;
    } else if (b <= zb) {
        int i = (b - 1) * 256 + t;
        if (i < N * MSGW / 4)
            ((float4*)g_MS)[i] = make_float4(0.f, 0.f, 0.f, 0.f);
    } else if (b <= zb + wb) {
        int id = (b - 1 - zb) * 256 + t;
        if (id < 128 * 192) {
            int k = id / 192, c = id - k * 192;
            float v;
            if (c < 32)      v = We[(size_t)k * MSGW + c];
            else if (c < 64) v = We[(size_t)(FN + k) * MSGW + (c - 32)];
            else             v = Wn[(size_t)k * FN + (c - 64)];
            __nv_bfloat16 h = __float2bfloat16(v);
            gWhi[id] = h;
            gWlo[id] = __float2bfloat16(v - __bfloat162float(h));
        }
    } else {
        int id = (b - 1 - zb - wb) * 256 + t;
        int row = id >> 5, q = id & 31;
        if (row < N) {
            float4 v = *(const float4*)&nf[(size_t)row * FN + 4 * q];
            __nv_bfloat162 h0 = bf2_hi(v.x, v.y), h1 = bf2_hi(v.z, v.w);
            size_t o = (size_t)row * FN + 4 * q;
            *(__nv_bfloat162*)&gAhi[o]     = h0;
            *(__nv_bfloat162*)&gAhi[o + 2] = h1;
            *(__nv_bfloat162*)&gAlo[o]     = bf2_lo(v.x, v.y, h0);
            *(__nv_bfloat162*)&gAlo[o + 2] = bf2_lo(v.z, v.w, h1);
        }
    }
}

// ---------------------------------------------------------------------------
// K1 (unchanged from R11): Q = nf @ fusedW, split-bf16 HMMA, double-buffered.
// ---------------------------------------------------------------------------
#define STG   36864
#define AHI_O 0
#define ALO_O 5120
#define WHI_O 10240
#define WLO_O 23040
#define G1_SMEM (2 * STG)

__global__ __launch_bounds__(256, 2) void k_gemm1(int N) {
    extern __shared__ char smem[];
    uint32_t sbase = sptr(smem);
    int t = threadIdx.x;
    int wid = t >> 5, lane = t & 31;
    int m0 = blockIdx.x * 64;
    int warp_m = wid & 1, warp_n = wid >> 1;
    int rbase = warp_m * 32, cbase = warp_n * 48;

    int arow = t >> 2, aq = t & 3;
    const __nv_bfloat16* aHiS = gAhi + (size_t)(m0 + arow) * FN + aq * 8;
    const __nv_bfloat16* aLoS = gAlo + (size_t)(m0 + arow) * FN + aq * 8;
    uint32_t aHiD = sbase + AHI_O + arow * 80 + aq * 16;
    uint32_t aLoD = sbase + ALO_O + arow * 80 + aq * 16;

    uint32_t aOff = (uint32_t)((rbase + (lane & 15)) * 80 + (lane >> 4) * 16);
    uint32_t wRow = (uint32_t)((lane & 7) + 8 * ((lane >> 3) & 1));
    uint32_t wOff = wRow * 400 + (uint32_t)(cbase + 8 * (lane >> 4)) * 2;

    float c[2][6][4];
#pragma unroll
    for (int mt = 0; mt < 2; mt++)
#pragma unroll
        for (int nt = 0; nt < 6; nt++)
#pragma unroll
            for (int i = 0; i < 4; i++) c[mt][nt][i] = 0.f;

    CP16(aHiD, aHiS);
    CP16(aLoD, aLoS);
#pragma unroll
    for (int j = 0; j < 3; j++) {
        int u = t + 256 * j;
        int wr = u / 24, cq = u - wr * 24;
        CP16(sbase + WHI_O + wr * 400 + cq * 16, gWhi + wr * 192 + cq * 8);
        CP16(sbase + WLO_O + wr * 400 + cq * 16, gWlo + wr * 192 + cq * 8);
    }
    CP_COMMIT();

#pragma unroll
    for (int ch = 0; ch < 4; ch++) {
        uint32_t stage = (uint32_t)(ch & 1) * STG;
        if (ch < 3) {
            int kc = (ch + 1) * 32;
            uint32_t nstage = (uint32_t)((ch + 1) & 1) * STG;
            CP16(aHiD + nstage, aHiS + kc);
            CP16(aLoD + nstage, aLoS + kc);
#pragma unroll
            for (int j = 0; j < 3; j++) {
                int u = t + 256 * j;
                int wr = u / 24, cq = u - wr * 24;
                CP16(sbase + WHI_O + nstage + wr * 400 + cq * 16,
                     gWhi + (kc + wr) * 192 + cq * 8);
                CP16(sbase + WLO_O + nstage + wr * 400 + cq * 16,
                     gWlo + (kc + wr) * 192 + cq * 8);
            }
            CP_COMMIT();
            CP_WAIT(1);
        } else {
            CP_WAIT(0);
        }
        __syncthreads();

        uint32_t aHiB = sbase + AHI_O + stage + aOff;
        uint32_t aLoB = sbase + ALO_O + stage + aOff;
        uint32_t wHiB = sbase + WHI_O + stage + wOff;
        uint32_t wLoB = sbase + WLO_O + stage + wOff;
#pragma unroll
        for (int ks = 0; ks < 2; ks++) {
            uint32_t ah[2][4], al[2][4];
            ldsm_x4(ah[0], aHiB + ks * 32);
            ldsm_x4(ah[1], aHiB + ks * 32 + 1280);
            ldsm_x4(al[0], aLoB + ks * 32);
            ldsm_x4(al[1], aLoB + ks * 32 + 1280);
#pragma unroll
            for (int j = 0; j < 3; j++) {
                uint32_t bh[4], bl[4];
                ldsm_x4t(bh, wHiB + ks * 6400 + j * 32);
                ldsm_x4t(bl, wLoB + ks * 6400 + j * 32);
#pragma unroll
                for (int mt = 0; mt < 2; mt++) {
                    mma16816(c[mt][2 * j],     ah[mt], bh[0], bh[1]);
                    mma16816(c[mt][2 * j],     al[mt], bh[0], bh[1]);
                    mma16816(c[mt][2 * j],     ah[mt], bl[0], bl[1]);
                    mma16816(c[mt][2 * j + 1], ah[mt], bh[2], bh[3]);
                    mma16816(c[mt][2 * j + 1], al[mt], bh[2], bh[3]);
                    mma16816(c[mt][2 * j + 1], ah[mt], bl[2], bl[3]);
                }
            }
        }
        __syncthreads();
    }

    int g = lane >> 2, tg = lane & 3;
#pragma unroll
    for (int mt = 0; mt < 2; mt++)
#pragma unroll
        for (int nt = 0; nt < 6; nt++) {
            int row = m0 + rbase + 16 * mt + g;
            int col = cbase + 8 * nt + 2 * tg;
            if (row < N)
                *(float2*)&g_Q[(size_t)row * QW + col] =
                    make_float2(c[mt][nt][0], c[mt][nt][1]);
            if (row + 8 < N)
                *(float2*)&g_Q[(size_t)(row + 8) * QW + col] =
                    make_float2(c[mt][nt][2], c[mt][nt][3]);
        }
}

// ---------------------------------------------------------------------------
// K2 v4 (HMMA): 256 edges/block.
//  Phase A: split ef tile + We2 to bf16 hi/lo in smem, 48 HMMA/warp
//           (warp = 32 edges x 32 cols), msg -> smem (overlays ef region).
//  Phase B: 8 lanes/edge float4 gather of Q + red.global.add.v4.f32.
// ---------------------------------------------------------------------------
__global__ __launch_bounds__(256, 3) void k_edges(const void* __restrict__ idx,
                                                  const float* __restrict__ ef,
                                                  const float* __restrict__ We,
                                                  const float* __restrict__ be,
                                                  int E) {
    __shared__ char sEdge[40960];            // ef hi/lo, later msg (36864B)
    __shared__ __nv_bfloat16 sW2Hi[32 * 40];
    __shared__ __nv_bfloat16 sW2Lo[32 * 40];
    __shared__ int   sN0[BE], sN1[BE];
    __shared__ float sBe[32];

    __nv_bfloat16* sEfHi = (__nv_bfloat16*)sEdge;     // [256][40]
    __nv_bfloat16* sEfLo = sEfHi + 256 * 40;
    float* sMsg = (float*)sEdge;                       // [256][36]

    int t  = threadIdx.x;
    int e0 = blockIdx.x * BE;
    int is64 = g_is64;

    {
        int e = e0 + t;
        if (e < E) {
            if (is64) {
                const long long* pp = (const long long*)idx;
                sN0[t] = (int)pp[e];
                sN1[t] = (int)pp[(size_t)E + e];
            } else {
                const int* pp = (const int*)idx;
                sN0[t] = pp[e];
                sN1[t] = pp[(size_t)E + e];
            }
        } else { sN0[t] = -1; sN1[t] = 0; }
    }
    // We2 split: 1024 values, 4/thread
#pragma unroll
    for (int id = t; id < 32 * 32; id += 256) {
        int k = id >> 5, c2 = id & 31;
        float v = We[(size_t)(2 * FN + k) * MSGW + c2];
        __nv_bfloat16 h = __float2bfloat16(v);
        sW2Hi[k * 40 + c2] = h;
        sW2Lo[k * 40 + c2] = __float2bfloat16(v - __bfloat162float(h));
    }
    if (t < 32) sBe[t] = be[t];
    // ef split: thread t owns edge e0+t
    {
        int e = e0 + t;
#pragma unroll
        for (int j = 0; j < 8; j++) {
            float4 v = (e < E) ? ((const float4*)ef)[(size_t)e * 8 + j]
                               : make_float4(0.f, 0.f, 0.f, 0.f);
            __nv_bfloat162 h0 = bf2_hi(v.x, v.y), h1 = bf2_hi(v.z, v.w);
            *(__nv_bfloat162*)&sEfHi[t * 40 + 4 * j]     = h0;
            *(__nv_bfloat162*)&sEfHi[t * 40 + 4 * j + 2] = h1;
            *(__nv_bfloat162*)&sEfLo[t * 40 + 4 * j]     = bf2_lo(v.x, v.y, h0);
            *(__nv_bfloat162*)&sEfLo[t * 40 + 4 * j + 2] = bf2_lo(v.z, v.w, h1);
        }
    }
    __syncthreads();

    int wid = t >> 5, lane = t & 31;
    uint32_t aOff = (uint32_t)((wid * 32 + (lane & 15)) * 80 + (lane >> 4) * 16);
    uint32_t aHiB = sptr(sEfHi) + aOff;
    uint32_t aLoB = sptr(sEfLo) + aOff;
    uint32_t wRow = (uint32_t)((lane & 7) + 8 * ((lane >> 3) & 1));
    uint32_t wOff = wRow * 80 + (uint32_t)(8 * (lane >> 4)) * 2;
    uint32_t wHiB = sptr(sW2Hi) + wOff;
    uint32_t wLoB = sptr(sW2Lo) + wOff;

    float c[2][4][4];
#pragma unroll
    for (int mt = 0; mt < 2; mt++)
#pragma unroll
        for (int nt = 0; nt < 4; nt++)
#pragma unroll
            for (int i = 0; i < 4; i++) c[mt][nt][i] = 0.f;

#pragma unroll
    for (int ks = 0; ks < 2; ks++) {
        uint32_t ah[2][4], al[2][4];
        ldsm_x4(ah[0], aHiB + ks * 32);
        ldsm_x4(ah[1], aHiB + ks * 32 + 1280);
        ldsm_x4(al[0], aLoB + ks * 32);
        ldsm_x4(al[1], aLoB + ks * 32 + 1280);
#pragma unroll
        for (int j = 0; j < 2; j++) {
            uint32_t bh[4], bl[4];
            ldsm_x4t(bh, wHiB + ks * 1280 + j * 32);
            ldsm_x4t(bl, wLoB + ks * 1280 + j * 32);
#pragma unroll
            for (int mt = 0; mt < 2; mt++) {
                mma16816(c[mt][2 * j],     ah[mt], bh[0], bh[1]);
                mma16816(c[mt][2 * j],     al[mt], bh[0], bh[1]);
                mma16816(c[mt][2 * j],     ah[mt], bl[0], bl[1]);
                mma16816(c[mt][2 * j + 1], ah[mt], bh[2], bh[3]);
                mma16816(c[mt][2 * j + 1], al[mt], bh[2], bh[3]);
                mma16816(c[mt][2 * j + 1], ah[mt], bl[2], bl[3]);
            }
        }
    }
    __syncthreads();   // all ldsm reads done before msg overlays ef

    int g = lane >> 2, tg = lane & 3;
#pragma unroll
    for (int mt = 0; mt < 2; mt++)
#pragma unroll
        for (int nt = 0; nt < 4; nt++) {
            int row = wid * 32 + 16 * mt + g;
            int col = 8 * nt + 2 * tg;
            *(float2*)&sMsg[row * 36 + col] = make_float2(c[mt][nt][0], c[mt][nt][1]);
            *(float2*)&sMsg[(row + 8) * 36 + col] =
                make_float2(c[mt][nt][2], c[mt][nt][3]);
        }
    __syncthreads();

    int sub = t & 7;
#pragma unroll
    for (int pass = 0; pass < 8; pass++) {
        int m  = pass * 32 + (t >> 3);
        int n0 = sN0[m];
        if (n0 >= 0) {
            int n1 = sN1[m];
            float4 mv = *(const float4*)&sMsg[m * 36 + sub * 4];
            float4 q0 = ((const float4*)&g_Q[(size_t)n0 * QW])[sub];
            float4 q1 = ((const float4*)&g_Q[(size_t)n1 * QW + 32])[sub];
            float4 bv = *(const float4*)&sBe[sub * 4];
            float x0 = fmaxf(mv.x + q0.x + q1.x + bv.x, 0.f);
            float x1 = fmaxf(mv.y + q0.y + q1.y + bv.y, 0.f);
            float x2 = fmaxf(mv.z + q0.z + q1.z + bv.z, 0.f);
            float x3 = fmaxf(mv.w + q0.w + q1.w + bv.w, 0.f);
            float* dst = &g_MS[(size_t)n0 * MSGW + sub * 4];
            asm volatile("red.global.add.v4.f32 [%0], {%1,%2,%3,%4};"
                         :: "l"(dst), "f"(x0), "f"(x1), "f"(x2), "f"(x3)
                         : "memory");
        }
    }
}

// ---------------------------------------------------------------------------
// K3 v2 (HMMA): out = relu(Q[:,64:192] + MS @ Wn1 + bn).
// Block 64 nodes x 128 cols. Warp = 16 nodes x 64 cols (warp_m=wid&3,
// warp_n=wid>>2). MS and Wn1 split to bf16 hi/lo in-kernel.
// ---------------------------------------------------------------------------
__global__ __launch_bounds__(256, 3) void k_nodes(const float* __restrict__ Wn,
                                                  const float* __restrict__ bn,
                                                  float* __restrict__ out,
                                                  int N) {
    __shared__ __nv_bfloat16 sMSHi[64 * 40];
    __shared__ __nv_bfloat16 sMSLo[64 * 40];
    __shared__ __nv_bfloat16 sW1Hi[32 * 136];
    __shared__ __nv_bfloat16 sW1Lo[32 * 136];
    __shared__ float sBn[128];

    int t  = threadIdx.x;
    int m0 = blockIdx.x * 64;
    int wid = t >> 5, lane = t & 31;
    int warp_m = wid & 3, warp_n = wid >> 2;

    // Wn1 split: 4096 vals, 16/thread (coalesced)
#pragma unroll
    for (int id = t; id < 32 * 128; id += 256) {
        int k = id >> 7, c2 = id & 127;
        float v = Wn[(size_t)(FN + k) * FN + c2];
        __nv_bfloat16 h = __float2bfloat16(v);
        sW1Hi[k * 136 + c2] = h;
        sW1Lo[k * 136 + c2] = __float2bfloat16(v - __bfloat162float(h));
    }
    // MS split: row = t>>2 (64 rows), cols (t&3)*8..+7
    {
        int row = t >> 2, c0 = (t & 3) * 8;
        int n = m0 + row;
#pragma unroll
        for (int j = 0; j < 2; j++) {
            float4 v = (n < N)
                ? *(const float4*)&g_MS[(size_t)n * MSGW + c0 + 4 * j]
                : make_float4(0.f, 0.f, 0.f, 0.f);
            __nv_bfloat162 h0 = bf2_hi(v.x, v.y), h1 = bf2_hi(v.z, v.w);
            *(__nv_bfloat162*)&sMSHi[row * 40 + c0 + 4 * j]     = h0;
            *(__nv_bfloat162*)&sMSHi[row * 40 + c0 + 4 * j + 2] = h1;
            *(__nv_bfloat162*)&sMSLo[row * 40 + c0 + 4 * j]     = bf2_lo(v.x, v.y, h0);
            *(__nv_bfloat162*)&sMSLo[row * 40 + c0 + 4 * j + 2] = bf2_lo(v.z, v.w, h1);
        }
    }
    if (t < 128) sBn[t] = bn[t];
    __syncthreads();

    uint32_t aOff = (uint32_t)((warp_m * 16 + (lane & 15)) * 80 + (lane >> 4) * 16);
    uint32_t aHiB = sptr(sMSHi) + aOff;
    uint32_t aLoB = sptr(sMSLo) + aOff;
    uint32_t wRow = (uint32_t)((lane & 7) + 8 * ((lane >> 3) & 1));
    uint32_t wOff = wRow * 272 + (uint32_t)(warp_n * 64 + 8 * (lane >> 4)) * 2;
    uint32_t wHiB = sptr(sW1Hi) + wOff;
    uint32_t wLoB = sptr(sW1Lo) + wOff;

    float c[8][4];
#pragma unroll
    for (int nt = 0; nt < 8; nt++)
#pragma unroll
        for (int i = 0; i < 4; i++) c[nt][i] = 0.f;

#pragma unroll
    for (int ks = 0; ks < 2; ks++) {
        uint32_t ah[4], al[4];
        ldsm_x4(ah, aHiB + ks * 32);
        ldsm_x4(al, aLoB + ks * 32);
#pragma unroll
        for (int j = 0; j < 4; j++) {
            uint32_t bh[4], bl[4];
            ldsm_x4t(bh, wHiB + ks * 4352 + j * 32);
            ldsm_x4t(bl, wLoB + ks * 4352 + j * 32);
            mma16816(c[2 * j],     ah, bh[0], bh[1]);
            mma16816(c[2 * j],     al, bh[0], bh[1]);
            mma16816(c[2 * j],     ah, bl[0], bl[1]);
            mma16816(c[2 * j + 1], ah, bh[2], bh[3]);
            mma16816(c[2 * j + 1], al, bh[2], bh[3]);
            mma16816(c[2 * j + 1], ah, bl[2], bl[3]);
        }
    }

    int g = lane >> 2, tg = lane & 3;
#pragma unroll
    for (int nt = 0; nt < 8; nt++) {
        int col = warp_n * 64 + 8 * nt + 2 * tg;
        float2 b = *(const float2*)&sBn[col];
#pragma unroll
        for (int half = 0; half < 2; half++) {
            int row = m0 + warp_m * 16 + g + 8 * half;
            if (row < N) {
                float2 q = *(const float2*)&g_Q[(size_t)row * QW + 64 + col];
                float2 o;
                o.x = fmaxf(c[nt][2 * half]     + q.x + b.x, 0.f);
                o.y = fmaxf(c[nt][2 * half + 1] + q.y + b.y, 0.f);
                *(float2*)&out[(size_t)row * FN + col] = o;
            }
        }
    }
}

// ---------------------------------------------------------------------------
extern "C" void kernel_launch(void* const* d_in, const int* in_sizes, int n_in,
                              void* d_out, int out_size) {
    const float* nf  = (const float*)d_in[0];
    const void*  idx = d_in[1];
    const float* ef  = (const float*)d_in[2];
    const float* We  = (const float*)d_in[3];
    const float* be  = (const float*)d_in[4];
    const float* Wn  = (const float*)d_in[5];
    const float* bn  = (const float*)d_in[6];
    float* out = (float*)d_out;

    int N = in_sizes[0] / FN;
    int E = in_sizes[2] / FE;

    static int smem_set = 0;
    if (!smem_set) {
        cudaFuncSetAttribute(k_gemm1, cudaFuncAttributeMaxDynamicSharedMemorySize,
                             G1_SMEM);
        smem_set = 1;
    }

    int zb = (N * MSGW / 4 + 255) / 256;
    int wb = (128 * 192 + 255) / 256;
    int ab = (N * 32 + 255) / 256;
    k_prep<<<1 + zb + wb + ab, 256>>>((const unsigned*)idx, nf, We, Wn, E, N, zb, wb);
    k_gemm1<<<(N + 63) / 64, 256, G1_SMEM>>>(N);
    k_edges<<<(E + BE - 1) / BE, 256>>>(idx, ef, We, be, E);
    k_nodes<<<(N + 63) / 64, 256>>>(Wn, bn, out, N);
}

// round 13
// speedup vs baseline: 3.2538x; 1.0372x over previous
#include <cuda_runtime.h>
#include <cuda_bf16.h>
#include <cstdint>

#define FN   128
#define FE   32
#define MSGW 32
#define QW   192          // Q cols: [0,32)=nf@We0, [32,64)=nf@We1, [64,192)=nf@Wn0
#define MAXN 50000
#define MAXNP 50048
#define BE   256

__device__ float g_Q[(size_t)MAXN * QW];
__device__ float g_MS[(size_t)MAXN * MSGW];
__device__ int   g_is64;
__device__ __nv_bfloat16 gAhi[(size_t)MAXNP * FN];
__device__ __nv_bfloat16 gAlo[(size_t)MAXNP * FN];
__device__ __nv_bfloat16 gWhi[128 * 192];
__device__ __nv_bfloat16 gWlo[128 * 192];

// ---------------------------------------------------------------------------
// helpers
// ---------------------------------------------------------------------------
static __device__ __forceinline__ uint32_t sptr(const void* p) {
    return (uint32_t)__cvta_generic_to_shared(p);
}
static __device__ __forceinline__ void ldsm_x4(uint32_t* r, uint32_t a) {
    asm volatile("ldmatrix.sync.aligned.m8n8.x4.shared.b16 {%0,%1,%2,%3},[%4];"
                 : "=r"(r[0]), "=r"(r[1]), "=r"(r[2]), "=r"(r[3]) : "r"(a));
}
static __device__ __forceinline__ void ldsm_x4t(uint32_t* r, uint32_t a) {
    asm volatile("ldmatrix.sync.aligned.m8n8.x4.trans.shared.b16 {%0,%1,%2,%3},[%4];"
                 : "=r"(r[0]), "=r"(r[1]), "=r"(r[2]), "=r"(r[3]) : "r"(a));
}
static __device__ __forceinline__ void mma16816(float* c, const uint32_t* a,
                                                uint32_t b0, uint32_t b1) {
    asm volatile(
        "mma.sync.aligned.m16n8k16.row.col.f32.bf16.bf16.f32 "
        "{%0,%1,%2,%3},{%4,%5,%6,%7},{%8,%9},{%0,%1,%2,%3};"
        : "+f"(c[0]), "+f"(c[1]), "+f"(c[2]), "+f"(c[3])
        : "r"(a[0]), "r"(a[1]), "r"(a[2]), "r"(a[3]), "r"(b0), "r"(b1));
}
#define CP16(dst, src) \
    asm volatile("cp.async.cg.shared.global [%0],[%1],16;" :: "r"(dst), "l"(src))
#define CP_COMMIT() asm volatile("cp.async.commit_group;" ::: "memory")
#define CP_WAIT(n)  asm volatile("cp.async.wait_group %0;" :: "n"(n) : "memory")

static __device__ __forceinline__ __nv_bfloat162 bf2_hi(float a, float b) {
    __nv_bfloat162 h; h.x = __float2bfloat16(a); h.y = __float2bfloat16(b); return h;
}
static __device__ __forceinline__ __nv_bfloat162 bf2_lo(float a, float b,
                                                        __nv_bfloat162 h) {
    __nv_bfloat162 l;
    l.x = __float2bfloat16(a - __bfloat162float(h.x));
    l.y = __float2bfloat16(b - __bfloat162float(h.y));
    return l;
}

// ---------------------------------------------------------------------------
// Mega-prep: detect idx dtype, zero g_MS, split W(fused) and A into bf16 hi/lo.
// ---------------------------------------------------------------------------
__global__ void k_prep(const unsigned* __restrict__ wds,
                       const float* __restrict__ nf,
                       const float* __restrict__ We,
                       const float* __restrict__ Wn,
                       int E, int N, int zb, int wb) {
    int b = blockIdx.x, t = threadIdx.x;
    if (b == 0) {
        __shared__ unsigned red[256];
        int sample = min(16384, E);
        unsigned v = 0;
        for (int i = t; i < sample; i += 256) v |= wds[2 * i + 1];
        red[t] = v;
        __syncthreads();
        for (int s = 128; s > 0; s >>= 1) {
            if (t < s) red[t] |= red[t + s];
            __syncthreads();
        }
        if (t == 0) g_is64 = (red[0] == 0u) ? 1 : 0;
    } else if (b <= zb) {
        int i = (b - 1) * 256 + t;
        if (i < N * MSGW / 4)
            ((float4*)g_MS)[i] = make_float4(0.f, 0.f, 0.f, 0.f);
    } else if (b <= zb + wb) {
        int id = (b - 1 - zb) * 256 + t;
        if (id < 128 * 192) {
            int k = id / 192, c = id - k * 192;
            float v;
            if (c < 32)      v = We[(size_t)k * MSGW + c];
            else if (c < 64) v = We[(size_t)(FN + k) * MSGW + (c - 32)];
            else             v = Wn[(size_t)k * FN + (c - 64)];
            __nv_bfloat16 h = __float2bfloat16(v);
            gWhi[id] = h;
            gWlo[id] = __float2bfloat16(v - __bfloat162float(h));
        }
    } else {
        int id = (b - 1 - zb - wb) * 256 + t;
        int row = id >> 5, q = id & 31;
        if (row < N) {
            float4 v = *(const float4*)&nf[(size_t)row * FN + 4 * q];
            __nv_bfloat162 h0 = bf2_hi(v.x, v.y), h1 = bf2_hi(v.z, v.w);
            size_t o = (size_t)row * FN + 4 * q;
            *(__nv_bfloat162*)&gAhi[o]     = h0;
            *(__nv_bfloat162*)&gAhi[o + 2] = h1;
            *(__nv_bfloat162*)&gAlo[o]     = bf2_lo(v.x, v.y, h0);
            *(__nv_bfloat162*)&gAlo[o + 2] = bf2_lo(v.z, v.w, h1);
        }
    }
}

// ---------------------------------------------------------------------------
// K1 (unchanged): Q = nf @ fusedW, split-bf16 HMMA, double-buffered cp.async.
// ---------------------------------------------------------------------------
#define STG   36864
#define AHI_O 0
#define ALO_O 5120
#define WHI_O 10240
#define WLO_O 23040
#define G1_SMEM (2 * STG)

__global__ __launch_bounds__(256, 2) void k_gemm1(int N) {
    extern __shared__ char smem[];
    uint32_t sbase = sptr(smem);
    int t = threadIdx.x;
    int wid = t >> 5, lane = t & 31;
    int m0 = blockIdx.x * 64;
    int warp_m = wid & 1, warp_n = wid >> 1;
    int rbase = warp_m * 32, cbase = warp_n * 48;

    int arow = t >> 2, aq = t & 3;
    const __nv_bfloat16* aHiS = gAhi + (size_t)(m0 + arow) * FN + aq * 8;
    const __nv_bfloat16* aLoS = gAlo + (size_t)(m0 + arow) * FN + aq * 8;
    uint32_t aHiD = sbase + AHI_O + arow * 80 + aq * 16;
    uint32_t aLoD = sbase + ALO_O + arow * 80 + aq * 16;

    uint32_t aOff = (uint32_t)((rbase + (lane & 15)) * 80 + (lane >> 4) * 16);
    uint32_t wRow = (uint32_t)((lane & 7) + 8 * ((lane >> 3) & 1));
    uint32_t wOff = wRow * 400 + (uint32_t)(cbase + 8 * (lane >> 4)) * 2;

    float c[2][6][4];
#pragma unroll
    for (int mt = 0; mt < 2; mt++)
#pragma unroll
        for (int nt = 0; nt < 6; nt++)
#pragma unroll
            for (int i = 0; i < 4; i++) c[mt][nt][i] = 0.f;

    CP16(aHiD, aHiS);
    CP16(aLoD, aLoS);
#pragma unroll
    for (int j = 0; j < 3; j++) {
        int u = t + 256 * j;
        int wr = u / 24, cq = u - wr * 24;
        CP16(sbase + WHI_O + wr * 400 + cq * 16, gWhi + wr * 192 + cq * 8);
        CP16(sbase + WLO_O + wr * 400 + cq * 16, gWlo + wr * 192 + cq * 8);
    }
    CP_COMMIT();

#pragma unroll
    for (int ch = 0; ch < 4; ch++) {
        uint32_t stage = (uint32_t)(ch & 1) * STG;
        if (ch < 3) {
            int kc = (ch + 1) * 32;
            uint32_t nstage = (uint32_t)((ch + 1) & 1) * STG;
            CP16(aHiD + nstage, aHiS + kc);
            CP16(aLoD + nstage, aLoS + kc);
#pragma unroll
            for (int j = 0; j < 3; j++) {
                int u = t + 256 * j;
                int wr = u / 24, cq = u - wr * 24;
                CP16(sbase + WHI_O + nstage + wr * 400 + cq * 16,
                     gWhi + (kc + wr) * 192 + cq * 8);
                CP16(sbase + WLO_O + nstage + wr * 400 + cq * 16,
                     gWlo + (kc + wr) * 192 + cq * 8);
            }
            CP_COMMIT();
            CP_WAIT(1);
        } else {
            CP_WAIT(0);
        }
        __syncthreads();

        uint32_t aHiB = sbase + AHI_O + stage + aOff;
        uint32_t aLoB = sbase + ALO_O + stage + aOff;
        uint32_t wHiB = sbase + WHI_O + stage + wOff;
        uint32_t wLoB = sbase + WLO_O + stage + wOff;
#pragma unroll
        for (int ks = 0; ks < 2; ks++) {
            uint32_t ah[2][4], al[2][4];
            ldsm_x4(ah[0], aHiB + ks * 32);
            ldsm_x4(ah[1], aHiB + ks * 32 + 1280);
            ldsm_x4(al[0], aLoB + ks * 32);
            ldsm_x4(al[1], aLoB + ks * 32 + 1280);
#pragma unroll
            for (int j = 0; j < 3; j++) {
                uint32_t bh[4], bl[4];
                ldsm_x4t(bh, wHiB + ks * 6400 + j * 32);
                ldsm_x4t(bl, wLoB + ks * 6400 + j * 32);
#pragma unroll
                for (int mt = 0; mt < 2; mt++) {
                    mma16816(c[mt][2 * j],     ah[mt], bh[0], bh[1]);
                    mma16816(c[mt][2 * j],     al[mt], bh[0], bh[1]);
                    mma16816(c[mt][2 * j],     ah[mt], bl[0], bl[1]);
                    mma16816(c[mt][2 * j + 1], ah[mt], bh[2], bh[3]);
                    mma16816(c[mt][2 * j + 1], al[mt], bh[2], bh[3]);
                    mma16816(c[mt][2 * j + 1], ah[mt], bl[2], bl[3]);
                }
            }
        }
        __syncthreads();
    }

    int g = lane >> 2, tg = lane & 3;
#pragma unroll
    for (int mt = 0; mt < 2; mt++)
#pragma unroll
        for (int nt = 0; nt < 6; nt++) {
            int row = m0 + rbase + 16 * mt + g;
            int col = cbase + 8 * nt + 2 * tg;
            if (row < N)
                *(float2*)&g_Q[(size_t)row * QW + col] =
                    make_float2(c[mt][nt][0], c[mt][nt][1]);
            if (row + 8 < N)
                *(float2*)&g_Q[(size_t)(row + 8) * QW + col] =
                    make_float2(c[mt][nt][2], c[mt][nt][3]);
        }
}

// ---------------------------------------------------------------------------
// K2 v5 (HMMA + MLP-batched scatter): 256 edges/block.
//  Phase A: split ef + We2 to bf16 hi/lo in smem, HMMA, msg -> smem.
//  Phase B: 2 waves x 4 edges; all 8 Q gathers issued before any RED.
// ---------------------------------------------------------------------------
__global__ __launch_bounds__(256, 3) void k_edges(const void* __restrict__ idx,
                                                  const float* __restrict__ ef,
                                                  const float* __restrict__ We,
                                                  const float* __restrict__ be,
                                                  int E) {
    __shared__ char sEdge[40960];            // ef hi/lo, later msg (36864B)
    __shared__ __nv_bfloat16 sW2Hi[32 * 40];
    __shared__ __nv_bfloat16 sW2Lo[32 * 40];
    __shared__ int   sN0[BE], sN1[BE];
    __shared__ float sBe[32];

    __nv_bfloat16* sEfHi = (__nv_bfloat16*)sEdge;     // [256][40]
    __nv_bfloat16* sEfLo = sEfHi + 256 * 40;
    float* sMsg = (float*)sEdge;                       // [256][36]

    int t  = threadIdx.x;
    int e0 = blockIdx.x * BE;
    int is64 = g_is64;

    {
        int e = e0 + t;
        if (e < E) {
            if (is64) {
                const long long* pp = (const long long*)idx;
                sN0[t] = (int)pp[e];
                sN1[t] = (int)pp[(size_t)E + e];
            } else {
                const int* pp = (const int*)idx;
                sN0[t] = pp[e];
                sN1[t] = pp[(size_t)E + e];
            }
        } else { sN0[t] = -1; sN1[t] = 0; }
    }
#pragma unroll
    for (int id = t; id < 32 * 32; id += 256) {
        int k = id >> 5, c2 = id & 31;
        float v = We[(size_t)(2 * FN + k) * MSGW + c2];
        __nv_bfloat16 h = __float2bfloat16(v);
        sW2Hi[k * 40 + c2] = h;
        sW2Lo[k * 40 + c2] = __float2bfloat16(v - __bfloat162float(h));
    }
    if (t < 32) sBe[t] = be[t];
    {
        int e = e0 + t;
#pragma unroll
        for (int j = 0; j < 8; j++) {
            float4 v = (e < E) ? ((const float4*)ef)[(size_t)e * 8 + j]
                               : make_float4(0.f, 0.f, 0.f, 0.f);
            __nv_bfloat162 h0 = bf2_hi(v.x, v.y), h1 = bf2_hi(v.z, v.w);
            *(__nv_bfloat162*)&sEfHi[t * 40 + 4 * j]     = h0;
            *(__nv_bfloat162*)&sEfHi[t * 40 + 4 * j + 2] = h1;
            *(__nv_bfloat162*)&sEfLo[t * 40 + 4 * j]     = bf2_lo(v.x, v.y, h0);
            *(__nv_bfloat162*)&sEfLo[t * 40 + 4 * j + 2] = bf2_lo(v.z, v.w, h1);
        }
    }
    __syncthreads();

    int wid = t >> 5, lane = t & 31;
    uint32_t aOff = (uint32_t)((wid * 32 + (lane & 15)) * 80 + (lane >> 4) * 16);
    uint32_t aHiB = sptr(sEfHi) + aOff;
    uint32_t aLoB = sptr(sEfLo) + aOff;
    uint32_t wRow = (uint32_t)((lane & 7) + 8 * ((lane >> 3) & 1));
    uint32_t wOff = wRow * 80 + (uint32_t)(8 * (lane >> 4)) * 2;
    uint32_t wHiB = sptr(sW2Hi) + wOff;
    uint32_t wLoB = sptr(sW2Lo) + wOff;

    float c[2][4][4];
#pragma unroll
    for (int mt = 0; mt < 2; mt++)
#pragma unroll
        for (int nt = 0; nt < 4; nt++)
#pragma unroll
            for (int i = 0; i < 4; i++) c[mt][nt][i] = 0.f;

#pragma unroll
    for (int ks = 0; ks < 2; ks++) {
        uint32_t ah[2][4], al[2][4];
        ldsm_x4(ah[0], aHiB + ks * 32);
        ldsm_x4(ah[1], aHiB + ks * 32 + 1280);
        ldsm_x4(al[0], aLoB + ks * 32);
        ldsm_x4(al[1], aLoB + ks * 32 + 1280);
#pragma unroll
        for (int j = 0; j < 2; j++) {
            uint32_t bh[4], bl[4];
            ldsm_x4t(bh, wHiB + ks * 1280 + j * 32);
            ldsm_x4t(bl, wLoB + ks * 1280 + j * 32);
#pragma unroll
            for (int mt = 0; mt < 2; mt++) {
                mma16816(c[mt][2 * j],     ah[mt], bh[0], bh[1]);
                mma16816(c[mt][2 * j],     al[mt], bh[0], bh[1]);
                mma16816(c[mt][2 * j],     ah[mt], bl[0], bl[1]);
                mma16816(c[mt][2 * j + 1], ah[mt], bh[2], bh[3]);
                mma16816(c[mt][2 * j + 1], al[mt], bh[2], bh[3]);
                mma16816(c[mt][2 * j + 1], ah[mt], bl[2], bl[3]);
            }
        }
    }
    __syncthreads();   // all ldsm reads done before msg overlays ef

    int g = lane >> 2, tg = lane & 3;
#pragma unroll
    for (int mt = 0; mt < 2; mt++)
#pragma unroll
        for (int nt = 0; nt < 4; nt++) {
            int row = wid * 32 + 16 * mt + g;
            int col = 8 * nt + 2 * tg;
            *(float2*)&sMsg[row * 36 + col] = make_float2(c[mt][nt][0], c[mt][nt][1]);
            *(float2*)&sMsg[(row + 8) * 36 + col] =
                make_float2(c[mt][nt][2], c[mt][nt][3]);
        }
    __syncthreads();

    // --- Phase B: 2 waves x 4 edges, loads batched for MLP=8 ---
    int sub = t & 7;
#pragma unroll
    for (int wave = 0; wave < 2; wave++) {
        int   n0v[4];
        float4 q0v[4], q1v[4], mv[4];
#pragma unroll
        for (int p = 0; p < 4; p++) {
            int m  = (wave * 4 + p) * 32 + (t >> 3);
            int n0 = sN0[m];
            int n1 = sN1[m];
            n0v[p] = n0;
            int a0 = (n0 < 0) ? 0 : n0;
            int a1 = (n0 < 0) ? 0 : n1;
            q0v[p] = ((const float4*)&g_Q[(size_t)a0 * QW])[sub];
            q1v[p] = ((const float4*)&g_Q[(size_t)a1 * QW + 32])[sub];
            mv[p]  = *(const float4*)&sMsg[m * 36 + sub * 4];
        }
        float4 bv = *(const float4*)&sBe[sub * 4];
#pragma unroll
        for (int p = 0; p < 4; p++) {
            if (n0v[p] >= 0) {
                float x0 = fmaxf(mv[p].x + q0v[p].x + q1v[p].x + bv.x, 0.f);
                float x1 = fmaxf(mv[p].y + q0v[p].y + q1v[p].y + bv.y, 0.f);
                float x2 = fmaxf(mv[p].z + q0v[p].z + q1v[p].z + bv.z, 0.f);
                float x3 = fmaxf(mv[p].w + q0v[p].w + q1v[p].w + bv.w, 0.f);
                float* dst = &g_MS[(size_t)n0v[p] * MSGW + sub * 4];
                asm volatile("red.global.add.v4.f32 [%0], {%1,%2,%3,%4};"
                             :: "l"(dst), "f"(x0), "f"(x1), "f"(x2), "f"(x3)
                             : "memory");
            }
        }
    }
}

// ---------------------------------------------------------------------------
// K3 (HMMA, unchanged except occupancy hint): out = relu(Q[:,64:192] + MS@Wn1 + bn).
// ---------------------------------------------------------------------------
__global__ __launch_bounds__(256, 4) void k_nodes(const float* __restrict__ Wn,
                                                  const float* __restrict__ bn,
                                                  float* __restrict__ out,
                                                  int N) {
    __shared__ __nv_bfloat16 sMSHi[64 * 40];
    __shared__ __nv_bfloat16 sMSLo[64 * 40];
    __shared__ __nv_bfloat16 sW1Hi[32 * 136];
    __shared__ __nv_bfloat16 sW1Lo[32 * 136];
    __shared__ float sBn[128];

    int t  = threadIdx.x;
    int m0 = blockIdx.x * 64;
    int wid = t >> 5, lane = t & 31;
    int warp_m = wid & 3, warp_n = wid >> 2;

#pragma unroll
    for (int id = t; id < 32 * 128; id += 256) {
        int k = id >> 7, c2 = id & 127;
        float v = Wn[(size_t)(FN + k) * FN + c2];
        __nv_bfloat16 h = __float2bfloat16(v);
        sW1Hi[k * 136 + c2] = h;
        sW1Lo[k * 136 + c2] = __float2bfloat16(v - __bfloat162float(h));
    }
    {
        int row = t >> 2, c0 = (t & 3) * 8;
        int n = m0 + row;
#pragma unroll
        for (int j = 0; j < 2; j++) {
            float4 v = (n < N)
                ? *(const float4*)&g_MS[(size_t)n * MSGW + c0 + 4 * j]
                : make_float4(0.f, 0.f, 0.f, 0.f);
            __nv_bfloat162 h0 = bf2_hi(v.x, v.y), h1 = bf2_hi(v.z, v.w);
            *(__nv_bfloat162*)&sMSHi[row * 40 + c0 + 4 * j]     = h0;
            *(__nv_bfloat162*)&sMSHi[row * 40 + c0 + 4 * j + 2] = h1;
            *(__nv_bfloat162*)&sMSLo[row * 40 + c0 + 4 * j]     = bf2_lo(v.x, v.y, h0);
            *(__nv_bfloat162*)&sMSLo[row * 40 + c0 + 4 * j + 2] = bf2_lo(v.z, v.w, h1);
        }
    }
    if (t < 128) sBn[t] = bn[t];
    __syncthreads();

    uint32_t aOff = (uint32_t)((warp_m * 16 + (lane & 15)) * 80 + (lane >> 4) * 16);
    uint32_t aHiB = sptr(sMSHi) + aOff;
    uint32_t aLoB = sptr(sMSLo) + aOff;
    uint32_t wRow = (uint32_t)((lane & 7) + 8 * ((lane >> 3) & 1));
    uint32_t wOff = wRow * 272 + (uint32_t)(warp_n * 64 + 8 * (lane >> 4)) * 2;
    uint32_t wHiB = sptr(sW1Hi) + wOff;
    uint32_t wLoB = sptr(sW1Lo) + wOff;

    float c[8][4];
#pragma unroll
    for (int nt = 0; nt < 8; nt++)
#pragma unroll
        for (int i = 0; i < 4; i++) c[nt][i] = 0.f;

#pragma unroll
    for (int ks = 0; ks < 2; ks++) {
        uint32_t ah[4], al[4];
        ldsm_x4(ah, aHiB + ks * 32);
        ldsm_x4(al, aLoB + ks * 32);
#pragma unroll
        for (int j = 0; j < 4; j++) {
            uint32_t bh[4], bl[4];
            ldsm_x4t(bh, wHiB + ks * 4352 + j * 32);
            ldsm_x4t(bl, wLoB + ks * 4352 + j * 32);
            mma16816(c[2 * j],     ah, bh[0], bh[1]);
            mma16816(c[2 * j],     al, bh[0], bh[1]);
            mma16816(c[2 * j],     ah, bl[0], bl[1]);
            mma16816(c[2 * j + 1], ah, bh[2], bh[3]);
            mma16816(c[2 * j + 1], al, bh[2], bh[3]);
            mma16816(c[2 * j + 1], ah, bl[2], bl[3]);
        }
    }

    int g = lane >> 2, tg = lane & 3;
#pragma unroll
    for (int nt = 0; nt < 8; nt++) {
        int col = warp_n * 64 + 8 * nt + 2 * tg;
        float2 b = *(const float2*)&sBn[col];
#pragma unroll
        for (int half = 0; half < 2; half++) {
            int row = m0 + warp_m * 16 + g + 8 * half;
            if (row < N) {
                float2 q = *(const float2*)&g_Q[(size_t)row * QW + 64 + col];
                float2 o;
                o.x = fmaxf(c[nt][2 * half]     + q.x + b.x, 0.f);
                o.y = fmaxf(c[nt][2 * half + 1] + q.y + b.y, 0.f);
                *(float2*)&out[(size_t)row * FN + col] = o;
            }
        }
    }
}

// ---------------------------------------------------------------------------
extern "C" void kernel_launch(void* const* d_in, const int* in_sizes, int n_in,
                              void* d_out, int out_size) {
    const float* nf  = (const float*)d_in[0];
    const void*  idx = d_in[1];
    const float* ef  = (const float*)d_in[2];
    const float* We  = (const float*)d_in[3];
    const float* be  = (const float*)d_in[4];
    const float* Wn  = (const float*)d_in[5];
    const float* bn  = (const float*)d_in[6];
    float* out = (float*)d_out;

    int N = in_sizes[0] / FN;
    int E = in_sizes[2] / FE;

    static int smem_set = 0;
    if (!smem_set) {
        cudaFuncSetAttribute(k_gemm1, cudaFuncAttributeMaxDynamicSharedMemorySize,
                             G1_SMEM);
        smem_set = 1;
    }

    int zb = (N * MSGW / 4 + 255) / 256;
    int wb = (128 * 192 + 255) / 256;
    int ab = (N * 32 + 255) / 256;
    k_prep<<<1 + zb + wb + ab, 256>>>((const unsigned*)idx, nf, We, Wn, E, N, zb, wb);
    k_gemm1<<<(N + 63) / 64, 256, G1_SMEM>>>(N);
    k_edges<<<(E + BE - 1) / BE, 256>>>(idx, ef, We, be, E);
    k_nodes<<<(N + 63) / 64, 256>>>(Wn, bn, out, N);
}

// round 15
// speedup vs baseline: 3.3141x; 1.0185x over previous
#include <cuda_runtime.h>
#include <cuda_bf16.h>
#include <cstdint>

#define FN   128
#define FE   32
#define MSGW 32
#define QW   192          // Q cols: [0,32)=nf@We0, [32,64)=nf@We1, [64,192)=nf@Wn0
#define MAXN 50000
#define BE   256

__device__ float g_Q[(size_t)MAXN * QW];
__device__ float g_MS[(size_t)MAXN * MSGW];
__device__ int   g_is64;
__device__ __nv_bfloat16 gWhi[128 * 192];
__device__ __nv_bfloat16 gWlo[128 * 192];

// ---------------------------------------------------------------------------
// helpers
// ---------------------------------------------------------------------------
static __device__ __forceinline__ uint32_t sptr(const void* p) {
    return (uint32_t)__cvta_generic_to_shared(p);
}
static __device__ __forceinline__ void ldsm_x4(uint32_t* r, uint32_t a) {
    asm volatile("ldmatrix.sync.aligned.m8n8.x4.shared.b16 {%0,%1,%2,%3},[%4];"
                 : "=r"(r[0]), "=r"(r[1]), "=r"(r[2]), "=r"(r[3]) : "r"(a));
}
static __device__ __forceinline__ void ldsm_x4t(uint32_t* r, uint32_t a) {
    asm volatile("ldmatrix.sync.aligned.m8n8.x4.trans.shared.b16 {%0,%1,%2,%3},[%4];"
                 : "=r"(r[0]), "=r"(r[1]), "=r"(r[2]), "=r"(r[3]) : "r"(a));
}
static __device__ __forceinline__ void mma16816(float* c, const uint32_t* a,
                                                uint32_t b0, uint32_t b1) {
    asm volatile(
        "mma.sync.aligned.m16n8k16.row.col.f32.bf16.bf16.f32 "
        "{%0,%1,%2,%3},{%4,%5,%6,%7},{%8,%9},{%0,%1,%2,%3};"
        : "+f"(c[0]), "+f"(c[1]), "+f"(c[2]), "+f"(c[3])
        : "r"(a[0]), "r"(a[1]), "r"(a[2]), "r"(a[3]), "r"(b0), "r"(b1));
}
#define CP16(dst, src) \
    asm volatile("cp.async.cg.shared.global [%0],[%1],16;" :: "r"(dst), "l"(src))
#define CP_COMMIT() asm volatile("cp.async.commit_group;" ::: "memory")
#define CP_WAIT(n)  asm volatile("cp.async.wait_group %0;" :: "n"(n) : "memory")

static __device__ __forceinline__ __nv_bfloat162 bf2_hi(float a, float b) {
    __nv_bfloat162 h; h.x = __float2bfloat16(a); h.y = __float2bfloat16(b); return h;
}
static __device__ __forceinline__ __nv_bfloat162 bf2_lo(float a, float b,
                                                        __nv_bfloat162 h) {
    __nv_bfloat162 l;
    l.x = __float2bfloat16(a - __bfloat162float(h.x));
    l.y = __float2bfloat16(b - __bfloat162float(h.y));
    return l;
}
static __device__ __forceinline__ uint32_t b2u(__nv_bfloat162 v) {
    uint32_t u; __builtin_memcpy(&u, &v, 4); return u;
}

// ---------------------------------------------------------------------------
// Prep (small): detect idx dtype, zero g_MS, split fused W into bf16 hi/lo.
// ---------------------------------------------------------------------------
__global__ void k_prep(const unsigned* __restrict__ wds,
                       const float* __restrict__ We,
                       const float* __restrict__ Wn,
                       int E, int N, int zb) {
    int b = blockIdx.x, t = threadIdx.x;
    if (b == 0) {
        __shared__ unsigned red[256];
        int sample = min(16384, E);
        unsigned v = 0;
        for (int i = t; i < sample; i += 256) v |= wds[2 * i + 1];
        red[t] = v;
        __syncthreads();
        for (int s = 128; s > 0; s >>= 1) {
            if (t < s) red[t] |= red[t + s];
            __syncthreads();
        }
        if (t == 0) g_is64 = (red[0] == 0u) ? 1 : 0;
    } else if (b <= zb) {
        int i = (b - 1) * 256 + t;
        if (i < N * MSGW / 4)
            ((float4*)g_MS)[i] = make_float4(0.f, 0.f, 0.f, 0.f);
    } else {
        int id = (b - 1 - zb) * 256 + t;
        if (id < 128 * 192) {
            int k = id / 192, c = id - k * 192;
            float v;
            if (c < 32)      v = We[(size_t)k * MSGW + c];
            else if (c < 64) v = We[(size_t)(FN + k) * MSGW + (c - 32)];
            else             v = Wn[(size_t)k * FN + (c - 64)];
            __nv_bfloat16 h = __float2bfloat16(v);
            gWhi[id] = h;
            gWlo[id] = __float2bfloat16(v - __bfloat162float(h));
        }
    }
}

// ---------------------------------------------------------------------------
// K1 v4 (fixed): Q = nf @ fusedW, split-bf16 HMMA.
// A: fp32 register-prefetch + in-kernel split. W: cp.async double-buffered.
// ---------------------------------------------------------------------------
#define STG   36864
#define AHI_O 0
#define ALO_O 5120
#define WHI_O 10240
#define WLO_O 23040
#define G1_SMEM (2 * STG)

__global__ __launch_bounds__(256, 2) void k_gemm1(const float* __restrict__ nf,
                                                  int N) {
    extern __shared__ char smem[];
    uint32_t sbase = sptr(smem);
    int t = threadIdx.x;
    int wid = t >> 5, lane = t & 31;
    int m0 = blockIdx.x * 64;
    int warp_m = wid & 1, warp_n = wid >> 1;
    int rbase = warp_m * 32, cbase = warp_n * 48;

    int arow = t >> 2, aq = t & 3;
    bool arowOK = (m0 + arow) < N;
    const float4* aSrc = (const float4*)(nf + (size_t)(m0 + arow) * FN) + aq * 2;
    uint32_t aDstOff = (uint32_t)(arow * 80 + aq * 16);

    uint32_t aOff = (uint32_t)((rbase + (lane & 15)) * 80 + (lane >> 4) * 16);
    uint32_t wRow = (uint32_t)((lane & 7) + 8 * ((lane >> 3) & 1));
    uint32_t wOff = wRow * 400 + (uint32_t)(cbase + 8 * (lane >> 4)) * 2;

    float c[2][6][4];
#pragma unroll
    for (int mt = 0; mt < 2; mt++)
#pragma unroll
        for (int nt = 0; nt < 6; nt++)
#pragma unroll
            for (int i = 0; i < 4; i++) c[mt][nt][i] = 0.f;

    float4 pa0 = make_float4(0.f, 0.f, 0.f, 0.f), pa1 = pa0;

    auto writeA = [&](uint32_t stageOff) {
        __nv_bfloat162 h0 = bf2_hi(pa0.x, pa0.y), h1 = bf2_hi(pa0.z, pa0.w);
        __nv_bfloat162 h2 = bf2_hi(pa1.x, pa1.y), h3 = bf2_hi(pa1.z, pa1.w);
        uint4 H = make_uint4(b2u(h0), b2u(h1), b2u(h2), b2u(h3));
        uint4 L = make_uint4(b2u(bf2_lo(pa0.x, pa0.y, h0)),
                             b2u(bf2_lo(pa0.z, pa0.w, h1)),
                             b2u(bf2_lo(pa1.x, pa1.y, h2)),
                             b2u(bf2_lo(pa1.z, pa1.w, h3)));
        *(uint4*)(smem + AHI_O + stageOff + aDstOff) = H;
        *(uint4*)(smem + ALO_O + stageOff + aDstOff) = L;
    };
    auto issueW = [&](int kc, uint32_t stageOff) {
#pragma unroll
        for (int j = 0; j < 3; j++) {
            int u = t + 256 * j;
            int wr = u / 24, cq = u - wr * 24;
            CP16(sbase + WHI_O + stageOff + wr * 400 + cq * 16,
                 gWhi + (kc + wr) * 192 + cq * 8);
            CP16(sbase + WLO_O + stageOff + wr * 400 + cq * 16,
                 gWlo + (kc + wr) * 192 + cq * 8);
        }
        CP_COMMIT();
    };

    // prologue
    if (arowOK) { pa0 = aSrc[0]; pa1 = aSrc[1]; }     // chunk 0 (fp32 cols 0..31)
    issueW(0, 0);
    writeA(0);
    if (arowOK) { pa0 = aSrc[8]; pa1 = aSrc[9]; }     // chunk 1 (cols 32..63)
    issueW(32, STG);

#pragma unroll
    for (int ch = 0; ch < 4; ch++) {
        uint32_t stage = (uint32_t)(ch & 1) * STG;
        if (ch < 3) CP_WAIT(1); else CP_WAIT(0);
        __syncthreads();

        uint32_t aHiB = sbase + AHI_O + stage + aOff;
        uint32_t aLoB = sbase + ALO_O + stage + aOff;
        uint32_t wHiB = sbase + WHI_O + stage + wOff;
        uint32_t wLoB = sbase + WLO_O + stage + wOff;
#pragma unroll
        for (int ks = 0; ks < 2; ks++) {
            uint32_t ah[2][4], al[2][4];
            ldsm_x4(ah[0], aHiB + ks * 32);
            ldsm_x4(ah[1], aHiB + ks * 32 + 1280);
            ldsm_x4(al[0], aLoB + ks * 32);
            ldsm_x4(al[1], aLoB + ks * 32 + 1280);
#pragma unroll
            for (int j = 0; j < 3; j++) {
                uint32_t bh[4], bl[4];
                ldsm_x4t(bh, wHiB + ks * 6400 + j * 32);
                ldsm_x4t(bl, wLoB + ks * 6400 + j * 32);
#pragma unroll
                for (int mt = 0; mt < 2; mt++) {
                    mma16816(c[mt][2 * j],     ah[mt], bh[0], bh[1]);
                    mma16816(c[mt][2 * j],     al[mt], bh[0], bh[1]);
                    mma16816(c[mt][2 * j],     ah[mt], bl[0], bl[1]);
                    mma16816(c[mt][2 * j + 1], ah[mt], bh[2], bh[3]);
                    mma16816(c[mt][2 * j + 1], al[mt], bh[2], bh[3]);
                    mma16816(c[mt][2 * j + 1], ah[mt], bl[2], bl[3]);
                }
            }
        }
        __syncthreads();

        if (ch < 3) {
            uint32_t nstage = (uint32_t)((ch + 1) & 1) * STG;
            writeA(nstage);                       // A(ch+1) -> stage(ch+1)
            if (ch < 2) {
                int kc = (ch + 2) * 32;
                if (arowOK) {                      // chunk ch+2: float4 off kc/4
                    pa0 = aSrc[kc >> 2];
                    pa1 = aSrc[(kc >> 2) + 1];
                }
                issueW(kc, stage);                // W(ch+2) -> stage(ch)
            }
        }
    }

    int g = lane >> 2, tg = lane & 3;
#pragma unroll
    for (int mt = 0; mt < 2; mt++)
#pragma unroll
        for (int nt = 0; nt < 6; nt++) {
            int row = m0 + rbase + 16 * mt + g;
            int col = cbase + 8 * nt + 2 * tg;
            if (row < N)
                *(float2*)&g_Q[(size_t)row * QW + col] =
                    make_float2(c[mt][nt][0], c[mt][nt][1]);
            if (row + 8 < N)
                *(float2*)&g_Q[(size_t)(row + 8) * QW + col] =
                    make_float2(c[mt][nt][2], c[mt][nt][3]);
        }
}

// ---------------------------------------------------------------------------
// K2 v6 (HMMA + 2-edge waves, 4 blocks/SM): 256 edges/block.
// ---------------------------------------------------------------------------
__global__ __launch_bounds__(256, 4) void k_edges(const void* __restrict__ idx,
                                                  const float* __restrict__ ef,
                                                  const float* __restrict__ We,
                                                  const float* __restrict__ be,
                                                  int E) {
    __shared__ char sEdge[40960];            // ef hi/lo, later msg (36864B)
    __shared__ __nv_bfloat16 sW2Hi[32 * 40];
    __shared__ __nv_bfloat16 sW2Lo[32 * 40];
    __shared__ int   sN0[BE], sN1[BE];
    __shared__ float sBe[32];

    __nv_bfloat16* sEfHi = (__nv_bfloat16*)sEdge;     // [256][40]
    __nv_bfloat16* sEfLo = sEfHi + 256 * 40;
    float* sMsg = (float*)sEdge;                       // [256][36]

    int t  = threadIdx.x;
    int e0 = blockIdx.x * BE;
    int is64 = g_is64;

    {
        int e = e0 + t;
        if (e < E) {
            if (is64) {
                const long long* pp = (const long long*)idx;
                sN0[t] = (int)pp[e];
                sN1[t] = (int)pp[(size_t)E + e];
            } else {
                const int* pp = (const int*)idx;
                sN0[t] = pp[e];
                sN1[t] = pp[(size_t)E + e];
            }
        } else { sN0[t] = -1; sN1[t] = 0; }
    }
#pragma unroll
    for (int id = t; id < 32 * 32; id += 256) {
        int k = id >> 5, c2 = id & 31;
        float v = We[(size_t)(2 * FN + k) * MSGW + c2];
        __nv_bfloat16 h = __float2bfloat16(v);
        sW2Hi[k * 40 + c2] = h;
        sW2Lo[k * 40 + c2] = __float2bfloat16(v - __bfloat162float(h));
    }
    if (t < 32) sBe[t] = be[t];
    {
        int e = e0 + t;
#pragma unroll
        for (int j = 0; j < 8; j++) {
            float4 v = (e < E) ? ((const float4*)ef)[(size_t)e * 8 + j]
                               : make_float4(0.f, 0.f, 0.f, 0.f);
            __nv_bfloat162 h0 = bf2_hi(v.x, v.y), h1 = bf2_hi(v.z, v.w);
            *(__nv_bfloat162*)&sEfHi[t * 40 + 4 * j]     = h0;
            *(__nv_bfloat162*)&sEfHi[t * 40 + 4 * j + 2] = h1;
            *(__nv_bfloat162*)&sEfLo[t * 40 + 4 * j]     = bf2_lo(v.x, v.y, h0);
            *(__nv_bfloat162*)&sEfLo[t * 40 + 4 * j + 2] = bf2_lo(v.z, v.w, h1);
        }
    }
    __syncthreads();

    int wid = t >> 5, lane = t & 31;
    uint32_t aOff = (uint32_t)((wid * 32 + (lane & 15)) * 80 + (lane >> 4) * 16);
    uint32_t aHiB = sptr(sEfHi) + aOff;
    uint32_t aLoB = sptr(sEfLo) + aOff;
    uint32_t wRow = (uint32_t)((lane & 7) + 8 * ((lane >> 3) & 1));
    uint32_t wOff = wRow * 80 + (uint32_t)(8 * (lane >> 4)) * 2;
    uint32_t wHiB = sptr(sW2Hi) + wOff;
    uint32_t wLoB = sptr(sW2Lo) + wOff;

    float c[2][4][4];
#pragma unroll
    for (int mt = 0; mt < 2; mt++)
#pragma unroll
        for (int nt = 0; nt < 4; nt++)
#pragma unroll
            for (int i = 0; i < 4; i++) c[mt][nt][i] = 0.f;

#pragma unroll
    for (int ks = 0; ks < 2; ks++) {
        uint32_t ah[2][4], al[2][4];
        ldsm_x4(ah[0], aHiB + ks * 32);
        ldsm_x4(ah[1], aHiB + ks * 32 + 1280);
        ldsm_x4(al[0], aLoB + ks * 32);
        ldsm_x4(al[1], aLoB + ks * 32 + 1280);
#pragma unroll
        for (int j = 0; j < 2; j++) {
            uint32_t bh[4], bl[4];
            ldsm_x4t(bh, wHiB + ks * 1280 + j * 32);
            ldsm_x4t(bl, wLoB + ks * 1280 + j * 32);
#pragma unroll
            for (int mt = 0; mt < 2; mt++) {
                mma16816(c[mt][2 * j],     ah[mt], bh[0], bh[1]);
                mma16816(c[mt][2 * j],     al[mt], bh[0], bh[1]);
                mma16816(c[mt][2 * j],     ah[mt], bl[0], bl[1]);
                mma16816(c[mt][2 * j + 1], ah[mt], bh[2], bh[3]);
                mma16816(c[mt][2 * j + 1], al[mt], bh[2], bh[3]);
                mma16816(c[mt][2 * j + 1], ah[mt], bl[2], bl[3]);
            }
        }
    }
    __syncthreads();

    int g = lane >> 2, tg = lane & 3;
#pragma unroll
    for (int mt = 0; mt < 2; mt++)
#pragma unroll
        for (int nt = 0; nt < 4; nt++) {
            int row = wid * 32 + 16 * mt + g;
            int col = 8 * nt + 2 * tg;
            *(float2*)&sMsg[row * 36 + col] = make_float2(c[mt][nt][0], c[mt][nt][1]);
            *(float2*)&sMsg[(row + 8) * 36 + col] =
                make_float2(c[mt][nt][2], c[mt][nt][3]);
        }
    __syncthreads();

    int sub = t & 7;
#pragma unroll
    for (int wave = 0; wave < 4; wave++) {
        int    n0v[2];
        float4 q0v[2], q1v[2], mv[2];
#pragma unroll
        for (int p = 0; p < 2; p++) {
            int m  = (wave * 2 + p) * 32 + (t >> 3);
            int n0 = sN0[m];
            int n1 = sN1[m];
            n0v[p] = n0;
            int a0 = (n0 < 0) ? 0 : n0;
            int a1 = (n0 < 0) ? 0 : n1;
            q0v[p] = ((const float4*)&g_Q[(size_t)a0 * QW])[sub];
            q1v[p] = ((const float4*)&g_Q[(size_t)a1 * QW + 32])[sub];
            mv[p]  = *(const float4*)&sMsg[m * 36 + sub * 4];
        }
        float4 bv = *(const float4*)&sBe[sub * 4];
#pragma unroll
        for (int p = 0; p < 2; p++) {
            if (n0v[p] >= 0) {
                float x0 = fmaxf(mv[p].x + q0v[p].x + q1v[p].x + bv.x, 0.f);
                float x1 = fmaxf(mv[p].y + q0v[p].y + q1v[p].y + bv.y, 0.f);
                float x2 = fmaxf(mv[p].z + q0v[p].z + q1v[p].z + bv.z, 0.f);
                float x3 = fmaxf(mv[p].w + q0v[p].w + q1v[p].w + bv.w, 0.f);
                float* dst = &g_MS[(size_t)n0v[p] * MSGW + sub * 4];
                asm volatile("red.global.add.v4.f32 [%0], {%1,%2,%3,%4};"
                             :: "l"(dst), "f"(x0), "f"(x1), "f"(x2), "f"(x3)
                             : "memory");
            }
        }
    }
}

// ---------------------------------------------------------------------------
// K3 (HMMA, unchanged): out = relu(Q[:,64:192] + MS@Wn1 + bn).
// ---------------------------------------------------------------------------
__global__ __launch_bounds__(256, 4) void k_nodes(const float* __restrict__ Wn,
                                                  const float* __restrict__ bn,
                                                  float* __restrict__ out,
                                                  int N) {
    __shared__ __nv_bfloat16 sMSHi[64 * 40];
    __shared__ __nv_bfloat16 sMSLo[64 * 40];
    __shared__ __nv_bfloat16 sW1Hi[32 * 136];
    __shared__ __nv_bfloat16 sW1Lo[32 * 136];
    __shared__ float sBn[128];

    int t  = threadIdx.x;
    int m0 = blockIdx.x * 64;
    int wid = t >> 5, lane = t & 31;
    int warp_m = wid & 3, warp_n = wid >> 2;

#pragma unroll
    for (int id = t; id < 32 * 128; id += 256) {
        int k = id >> 7, c2 = id & 127;
        float v = Wn[(size_t)(FN + k) * FN + c2];
        __nv_bfloat16 h = __float2bfloat16(v);
        sW1Hi[k * 136 + c2] = h;
        sW1Lo[k * 136 + c2] = __float2bfloat16(v - __bfloat162float(h));
    }
    {
        int row = t >> 2, c0 = (t & 3) * 8;
        int n = m0 + row;
#pragma unroll
        for (int j = 0; j < 2; j++) {
            float4 v = (n < N)
                ? *(const float4*)&g_MS[(size_t)n * MSGW + c0 + 4 * j]
                : make_float4(0.f, 0.f, 0.f, 0.f);
            __nv_bfloat162 h0 = bf2_hi(v.x, v.y), h1 = bf2_hi(v.z, v.w);
            *(__nv_bfloat162*)&sMSHi[row * 40 + c0 + 4 * j]     = h0;
            *(__nv_bfloat162*)&sMSHi[row * 40 + c0 + 4 * j + 2] = h1;
            *(__nv_bfloat162*)&sMSLo[row * 40 + c0 + 4 * j]     = bf2_lo(v.x, v.y, h0);
            *(__nv_bfloat162*)&sMSLo[row * 40 + c0 + 4 * j + 2] = bf2_lo(v.z, v.w, h1);
        }
    }
    if (t < 128) sBn[t] = bn[t];
    __syncthreads();

    uint32_t aOff = (uint32_t)((warp_m * 16 + (lane & 15)) * 80 + (lane >> 4) * 16);
    uint32_t aHiB = sptr(sMSHi) + aOff;
    uint32_t aLoB = sptr(sMSLo) + aOff;
    uint32_t wRow = (uint32_t)((lane & 7) + 8 * ((lane >> 3) & 1));
    uint32_t wOff = wRow * 272 + (uint32_t)(warp_n * 64 + 8 * (lane >> 4)) * 2;
    uint32_t wHiB = sptr(sW1Hi) + wOff;
    uint32_t wLoB = sptr(sW1Lo) + wOff;

    float c[8][4];
#pragma unroll
    for (int nt = 0; nt < 8; nt++)
#pragma unroll
        for (int i = 0; i < 4; i++) c[nt][i] = 0.f;

#pragma unroll
    for (int ks = 0; ks < 2; ks++) {
        uint32_t ah[4], al[4];
        ldsm_x4(ah, aHiB + ks * 32);
        ldsm_x4(al, aLoB + ks * 32);
#pragma unroll
        for (int j = 0; j < 4; j++) {
            uint32_t bh[4], bl[4];
            ldsm_x4t(bh, wHiB + ks * 4352 + j * 32);
            ldsm_x4t(bl, wLoB + ks * 4352 + j * 32);
            mma16816(c[2 * j],     ah, bh[0], bh[1]);
            mma16816(c[2 * j],     al, bh[0], bh[1]);
            mma16816(c[2 * j],     ah, bl[0], bl[1]);
            mma16816(c[2 * j + 1], ah, bh[2], bh[3]);
            mma16816(c[2 * j + 1], al, bh[2], bh[3]);
            mma16816(c[2 * j + 1], ah, bl[2], bl[3]);
        }
    }

    int g = lane >> 2, tg = lane & 3;
#pragma unroll
    for (int nt = 0; nt < 8; nt++) {
        int col = warp_n * 64 + 8 * nt + 2 * tg;
        float2 b = *(const float2*)&sBn[col];
#pragma unroll
        for (int half = 0; half < 2; half++) {
            int row = m0 + warp_m * 16 + g + 8 * half;
            if (row < N) {
                float2 q = *(const float2*)&g_Q[(size_t)row * QW + 64 + col];
                float2 o;
                o.x = fmaxf(c[nt][2 * half]     + q.x + b.x, 0.f);
                o.y = fmaxf(c[nt][2 * half + 1] + q.y + b.y, 0.f);
                *(float2*)&out[(size_t)row * FN + col] = o;
            }
        }
    }
}

// ---------------------------------------------------------------------------
extern "C" void kernel_launch(void* const* d_in, const int* in_sizes, int n_in,
                              void* d_out, int out_size) {
    const float* nf  = (const float*)d_in[0];
    const void*  idx = d_in[1];
    const float* ef  = (const float*)d_in[2];
    const float* We  = (const float*)d_in[3];
    const float* be  = (const float*)d_in[4];
    const float* Wn  = (const float*)d_in[5];
    const float* bn  = (const float*)d_in[6];
    float* out = (float*)d_out;

    int N = in_sizes[0] / FN;
    int E = in_sizes[2] / FE;

    static int smem_set = 0;
    if (!smem_set) {
        cudaFuncSetAttribute(k_gemm1, cudaFuncAttributeMaxDynamicSharedMemorySize,
                             G1_SMEM);
        smem_set = 1;
    }

    int zb = (N * MSGW / 4 + 255) / 256;
    int wb = (128 * 192 + 255) / 256;
    k_prep<<<1 + zb + wb, 256>>>((const unsigned*)idx, We, Wn, E, N, zb);
    k_gemm1<<<(N + 63) / 64, 256, G1_SMEM>>>(nf, N);
    k_edges<<<(E + BE - 1) / BE, 256>>>(idx, ef, We, be, E);
    k_nodes<<<(N + 63) / 64, 256>>>(Wn, bn, out, N);
}

// round 16
// speedup vs baseline: 3.3676x; 1.0162x over previous
#include <cuda_runtime.h>
#include <cuda_bf16.h>
#include <cstdint>

#define FN   128
#define FE   32
#define MSGW 32
#define QW   192          // Q cols: [0,32)=nf@We0, [32,64)=nf@We1, [64,192)=nf@Wn0
#define MAXN 50000
#define BE   256

__device__ float g_Q[(size_t)MAXN * QW];
__device__ float g_MS[(size_t)MAXN * MSGW];
__device__ int   g_is64;
__device__ __nv_bfloat16 gWhi[128 * 192];
__device__ __nv_bfloat16 gWlo[128 * 192];

// ---------------------------------------------------------------------------
// helpers
// ---------------------------------------------------------------------------
static __device__ __forceinline__ uint32_t sptr(const void* p) {
    return (uint32_t)__cvta_generic_to_shared(p);
}
static __device__ __forceinline__ void ldsm_x4(uint32_t* r, uint32_t a) {
    asm volatile("ldmatrix.sync.aligned.m8n8.x4.shared.b16 {%0,%1,%2,%3},[%4];"
                 : "=r"(r[0]), "=r"(r[1]), "=r"(r[2]), "=r"(r[3]) : "r"(a));
}
static __device__ __forceinline__ void ldsm_x4t(uint32_t* r, uint32_t a) {
    asm volatile("ldmatrix.sync.aligned.m8n8.x4.trans.shared.b16 {%0,%1,%2,%3},[%4];"
                 : "=r"(r[0]), "=r"(r[1]), "=r"(r[2]), "=r"(r[3]) : "r"(a));
}
static __device__ __forceinline__ void mma16816(float* c, const uint32_t* a,
                                                uint32_t b0, uint32_t b1) {
    asm volatile(
        "mma.sync.aligned.m16n8k16.row.col.f32.bf16.bf16.f32 "
        "{%0,%1,%2,%3},{%4,%5,%6,%7},{%8,%9},{%0,%1,%2,%3};"
        : "+f"(c[0]), "+f"(c[1]), "+f"(c[2]), "+f"(c[3])
        : "r"(a[0]), "r"(a[1]), "r"(a[2]), "r"(a[3]), "r"(b0), "r"(b1));
}
#define CP16(dst, src) \
    asm volatile("cp.async.cg.shared.global [%0],[%1],16;" :: "r"(dst), "l"(src))
#define CP_COMMIT() asm volatile("cp.async.commit_group;" ::: "memory")
#define CP_WAIT(n)  asm volatile("cp.async.wait_group %0;" :: "n"(n) : "memory")

static __device__ __forceinline__ __nv_bfloat162 bf2_hi(float a, float b) {
    __nv_bfloat162 h; h.x = __float2bfloat16(a); h.y = __float2bfloat16(b); return h;
}
static __device__ __forceinline__ __nv_bfloat162 bf2_lo(float a, float b,
                                                        __nv_bfloat162 h) {
    __nv_bfloat162 l;
    l.x = __float2bfloat16(a - __bfloat162float(h.x));
    l.y = __float2bfloat16(b - __bfloat162float(h.y));
    return l;
}
static __device__ __forceinline__ uint32_t b2u(__nv_bfloat162 v) {
    uint32_t u; __builtin_memcpy(&u, &v, 4); return u;
}

// ---------------------------------------------------------------------------
// Prep (small): detect idx dtype, zero g_MS, split fused W into bf16 hi/lo.
// ---------------------------------------------------------------------------
__global__ void k_prep(const unsigned* __restrict__ wds,
                       const float* __restrict__ We,
                       const float* __restrict__ Wn,
                       int E, int N, int zb) {
    int b = blockIdx.x, t = threadIdx.x;
    if (b == 0) {
        __shared__ unsigned red[256];
        int sample = min(16384, E);
        unsigned v = 0;
        for (int i = t; i < sample; i += 256) v |= wds[2 * i + 1];
        red[t] = v;
        __syncthreads();
        for (int s = 128; s > 0; s >>= 1) {
            if (t < s) red[t] |= red[t + s];
            __syncthreads();
        }
        if (t == 0) g_is64 = (red[0] == 0u) ? 1 : 0;
    } else if (b <= zb) {
        int i = (b - 1) * 256 + t;
        if (i < N * MSGW / 4)
            ((float4*)g_MS)[i] = make_float4(0.f, 0.f, 0.f, 0.f);
    } else {
        int id = (b - 1 - zb) * 256 + t;
        if (id < 128 * 192) {
            int k = id / 192, c = id - k * 192;
            float v;
            if (c < 32)      v = We[(size_t)k * MSGW + c];
            else if (c < 64) v = We[(size_t)(FN + k) * MSGW + (c - 32)];
            else             v = Wn[(size_t)k * FN + (c - 64)];
            __nv_bfloat16 h = __float2bfloat16(v);
            gWhi[id] = h;
            gWlo[id] = __float2bfloat16(v - __bfloat162float(h));
        }
    }
}

// ---------------------------------------------------------------------------
// K1 v4: Q = nf @ fusedW, split-bf16 HMMA.
// A: fp32 register-prefetch + in-kernel split. W: cp.async double-buffered.
// ---------------------------------------------------------------------------
#define STG   36864
#define AHI_O 0
#define ALO_O 5120
#define WHI_O 10240
#define WLO_O 23040
#define G1_SMEM (2 * STG)

__global__ __launch_bounds__(256, 2) void k_gemm1(const float* __restrict__ nf,
                                                  int N) {
    extern __shared__ char smem[];
    uint32_t sbase = sptr(smem);
    int t = threadIdx.x;
    int wid = t >> 5, lane = t & 31;
    int m0 = blockIdx.x * 64;
    int warp_m = wid & 1, warp_n = wid >> 1;
    int rbase = warp_m * 32, cbase = warp_n * 48;

    int arow = t >> 2, aq = t & 3;
    bool arowOK = (m0 + arow) < N;
    const float4* aSrc = (const float4*)(nf + (size_t)(m0 + arow) * FN) + aq * 2;
    uint32_t aDstOff = (uint32_t)(arow * 80 + aq * 16);

    uint32_t aOff = (uint32_t)((rbase + (lane & 15)) * 80 + (lane >> 4) * 16);
    uint32_t wRow = (uint32_t)((lane & 7) + 8 * ((lane >> 3) & 1));
    uint32_t wOff = wRow * 400 + (uint32_t)(cbase + 8 * (lane >> 4)) * 2;

    float c[2][6][4];
#pragma unroll
    for (int mt = 0; mt < 2; mt++)
#pragma unroll
        for (int nt = 0; nt < 6; nt++)
#pragma unroll
            for (int i = 0; i < 4; i++) c[mt][nt][i] = 0.f;

    float4 pa0 = make_float4(0.f, 0.f, 0.f, 0.f), pa1 = pa0;

    auto writeA = [&](uint32_t stageOff) {
        __nv_bfloat162 h0 = bf2_hi(pa0.x, pa0.y), h1 = bf2_hi(pa0.z, pa0.w);
        __nv_bfloat162 h2 = bf2_hi(pa1.x, pa1.y), h3 = bf2_hi(pa1.z, pa1.w);
        uint4 H = make_uint4(b2u(h0), b2u(h1), b2u(h2), b2u(h3));
        uint4 L = make_uint4(b2u(bf2_lo(pa0.x, pa0.y, h0)),
                             b2u(bf2_lo(pa0.z, pa0.w, h1)),
                             b2u(bf2_lo(pa1.x, pa1.y, h2)),
                             b2u(bf2_lo(pa1.z, pa1.w, h3)));
        *(uint4*)(smem + AHI_O + stageOff + aDstOff) = H;
        *(uint4*)(smem + ALO_O + stageOff + aDstOff) = L;
    };
    auto issueW = [&](int kc, uint32_t stageOff) {
#pragma unroll
        for (int j = 0; j < 3; j++) {
            int u = t + 256 * j;
            int wr = u / 24, cq = u - wr * 24;
            CP16(sbase + WHI_O + stageOff + wr * 400 + cq * 16,
                 gWhi + (kc + wr) * 192 + cq * 8);
            CP16(sbase + WLO_O + stageOff + wr * 400 + cq * 16,
                 gWlo + (kc + wr) * 192 + cq * 8);
        }
        CP_COMMIT();
    };

    // prologue
    if (arowOK) { pa0 = aSrc[0]; pa1 = aSrc[1]; }     // chunk 0
    issueW(0, 0);
    writeA(0);
    if (arowOK) { pa0 = aSrc[8]; pa1 = aSrc[9]; }     // chunk 1
    issueW(32, STG);

#pragma unroll
    for (int ch = 0; ch < 4; ch++) {
        uint32_t stage = (uint32_t)(ch & 1) * STG;
        if (ch < 3) CP_WAIT(1); else CP_WAIT(0);
        __syncthreads();

        uint32_t aHiB = sbase + AHI_O + stage + aOff;
        uint32_t aLoB = sbase + ALO_O + stage + aOff;
        uint32_t wHiB = sbase + WHI_O + stage + wOff;
        uint32_t wLoB = sbase + WLO_O + stage + wOff;
#pragma unroll
        for (int ks = 0; ks < 2; ks++) {
            uint32_t ah[2][4], al[2][4];
            ldsm_x4(ah[0], aHiB + ks * 32);
            ldsm_x4(ah[1], aHiB + ks * 32 + 1280);
            ldsm_x4(al[0], aLoB + ks * 32);
            ldsm_x4(al[1], aLoB + ks * 32 + 1280);
#pragma unroll
            for (int j = 0; j < 3; j++) {
                uint32_t bh[4], bl[4];
                ldsm_x4t(bh, wHiB + ks * 6400 + j * 32);
                ldsm_x4t(bl, wLoB + ks * 6400 + j * 32);
#pragma unroll
                for (int mt = 0; mt < 2; mt++) {
                    mma16816(c[mt][2 * j],     ah[mt], bh[0], bh[1]);
                    mma16816(c[mt][2 * j],     al[mt], bh[0], bh[1]);
                    mma16816(c[mt][2 * j],     ah[mt], bl[0], bl[1]);
                    mma16816(c[mt][2 * j + 1], ah[mt], bh[2], bh[3]);
                    mma16816(c[mt][2 * j + 1], al[mt], bh[2], bh[3]);
                    mma16816(c[mt][2 * j + 1], ah[mt], bl[2], bl[3]);
                }
            }
        }
        __syncthreads();

        if (ch < 3) {
            uint32_t nstage = (uint32_t)((ch + 1) & 1) * STG;
            writeA(nstage);
            if (ch < 2) {
                int kc = (ch + 2) * 32;
                if (arowOK) {
                    pa0 = aSrc[kc >> 2];
                    pa1 = aSrc[(kc >> 2) + 1];
                }
                issueW(kc, stage);
            }
        }
    }

    int g = lane >> 2, tg = lane & 3;
#pragma unroll
    for (int mt = 0; mt < 2; mt++)
#pragma unroll
        for (int nt = 0; nt < 6; nt++) {
            int row = m0 + rbase + 16 * mt + g;
            int col = cbase + 8 * nt + 2 * tg;
            if (row < N)
                *(float2*)&g_Q[(size_t)row * QW + col] =
                    make_float2(c[mt][nt][0], c[mt][nt][1]);
            if (row + 8 < N)
                *(float2*)&g_Q[(size_t)(row + 8) * QW + col] =
                    make_float2(c[mt][nt][2], c[mt][nt][3]);
        }
}

// ---------------------------------------------------------------------------
// K2 v7 (HMMA + 2 waves x 4 edges, 3 blocks/SM): 256 edges/block.
// ---------------------------------------------------------------------------
__global__ __launch_bounds__(256, 3) void k_edges(const void* __restrict__ idx,
                                                  const float* __restrict__ ef,
                                                  const float* __restrict__ We,
                                                  const float* __restrict__ be,
                                                  int E) {
    __shared__ char sEdge[40960];            // ef hi/lo, later msg (36864B)
    __shared__ __nv_bfloat16 sW2Hi[32 * 40];
    __shared__ __nv_bfloat16 sW2Lo[32 * 40];
    __shared__ int   sN0[BE], sN1[BE];
    __shared__ float sBe[32];

    __nv_bfloat16* sEfHi = (__nv_bfloat16*)sEdge;     // [256][40]
    __nv_bfloat16* sEfLo = sEfHi + 256 * 40;
    float* sMsg = (float*)sEdge;                       // [256][36]

    int t  = threadIdx.x;
    int e0 = blockIdx.x * BE;
    int is64 = g_is64;

    {
        int e = e0 + t;
        if (e < E) {
            if (is64) {
                const long long* pp = (const long long*)idx;
                sN0[t] = (int)pp[e];
                sN1[t] = (int)pp[(size_t)E + e];
            } else {
                const int* pp = (const int*)idx;
                sN0[t] = pp[e];
                sN1[t] = pp[(size_t)E + e];
            }
        } else { sN0[t] = -1; sN1[t] = 0; }
    }
#pragma unroll
    for (int id = t; id < 32 * 32; id += 256) {
        int k = id >> 5, c2 = id & 31;
        float v = We[(size_t)(2 * FN + k) * MSGW + c2];
        __nv_bfloat16 h = __float2bfloat16(v);
        sW2Hi[k * 40 + c2] = h;
        sW2Lo[k * 40 + c2] = __float2bfloat16(v - __bfloat162float(h));
    }
    if (t < 32) sBe[t] = be[t];
    {
        int e = e0 + t;
#pragma unroll
        for (int j = 0; j < 8; j++) {
            float4 v = (e < E) ? ((const float4*)ef)[(size_t)e * 8 + j]
                               : make_float4(0.f, 0.f, 0.f, 0.f);
            __nv_bfloat162 h0 = bf2_hi(v.x, v.y), h1 = bf2_hi(v.z, v.w);
            *(__nv_bfloat162*)&sEfHi[t * 40 + 4 * j]     = h0;
            *(__nv_bfloat162*)&sEfHi[t * 40 + 4 * j + 2] = h1;
            *(__nv_bfloat162*)&sEfLo[t * 40 + 4 * j]     = bf2_lo(v.x, v.y, h0);
            *(__nv_bfloat162*)&sEfLo[t * 40 + 4 * j + 2] = bf2_lo(v.z, v.w, h1);
        }
    }
    __syncthreads();

    int wid = t >> 5, lane = t & 31;
    uint32_t aOff = (uint32_t)((wid * 32 + (lane & 15)) * 80 + (lane >> 4) * 16);
    uint32_t aHiB = sptr(sEfHi) + aOff;
    uint32_t aLoB = sptr(sEfLo) + aOff;
    uint32_t wRow = (uint32_t)((lane & 7) + 8 * ((lane >> 3) & 1));
    uint32_t wOff = wRow * 80 + (uint32_t)(8 * (lane >> 4)) * 2;
    uint32_t wHiB = sptr(sW2Hi) + wOff;
    uint32_t wLoB = sptr(sW2Lo) + wOff;

    float c[2][4][4];
#pragma unroll
    for (int mt = 0; mt < 2; mt++)
#pragma unroll
        for (int nt = 0; nt < 4; nt++)
#pragma unroll
            for (int i = 0; i < 4; i++) c[mt][nt][i] = 0.f;

#pragma unroll
    for (int ks = 0; ks < 2; ks++) {
        uint32_t ah[2][4], al[2][4];
        ldsm_x4(ah[0], aHiB + ks * 32);
        ldsm_x4(ah[1], aHiB + ks * 32 + 1280);
        ldsm_x4(al[0], aLoB + ks * 32);
        ldsm_x4(al[1], aLoB + ks * 32 + 1280);
#pragma unroll
        for (int j = 0; j < 2; j++) {
            uint32_t bh[4], bl[4];
            ldsm_x4t(bh, wHiB + ks * 1280 + j * 32);
            ldsm_x4t(bl, wLoB + ks * 1280 + j * 32);
#pragma unroll
            for (int mt = 0; mt < 2; mt++) {
                mma16816(c[mt][2 * j],     ah[mt], bh[0], bh[1]);
                mma16816(c[mt][2 * j],     al[mt], bh[0], bh[1]);
                mma16816(c[mt][2 * j],     ah[mt], bl[0], bl[1]);
                mma16816(c[mt][2 * j + 1], ah[mt], bh[2], bh[3]);
                mma16816(c[mt][2 * j + 1], al[mt], bh[2], bh[3]);
                mma16816(c[mt][2 * j + 1], ah[mt], bl[2], bl[3]);
            }
        }
    }
    __syncthreads();

    int g = lane >> 2, tg = lane & 3;
#pragma unroll
    for (int mt = 0; mt < 2; mt++)
#pragma unroll
        for (int nt = 0; nt < 4; nt++) {
            int row = wid * 32 + 16 * mt + g;
            int col = 8 * nt + 2 * tg;
            *(float2*)&sMsg[row * 36 + col] = make_float2(c[mt][nt][0], c[mt][nt][1]);
            *(float2*)&sMsg[(row + 8) * 36 + col] =
                make_float2(c[mt][nt][2], c[mt][nt][3]);
        }
    __syncthreads();

    // --- Phase B: 2 waves x 4 edges, loads batched for MLP=8 ---
    int sub = t & 7;
#pragma unroll
    for (int wave = 0; wave < 2; wave++) {
        int    n0v[4];
        float4 q0v[4], q1v[4], mv[4];
#pragma unroll
        for (int p = 0; p < 4; p++) {
            int m  = (wave * 4 + p) * 32 + (t >> 3);
            int n0 = sN0[m];
            int n1 = sN1[m];
            n0v[p] = n0;
            int a0 = (n0 < 0) ? 0 : n0;
            int a1 = (n0 < 0) ? 0 : n1;
            q0v[p] = ((const float4*)&g_Q[(size_t)a0 * QW])[sub];
            q1v[p] = ((const float4*)&g_Q[(size_t)a1 * QW + 32])[sub];
            mv[p]  = *(const float4*)&sMsg[m * 36 + sub * 4];
        }
        float4 bv = *(const float4*)&sBe[sub * 4];
#pragma unroll
        for (int p = 0; p < 4; p++) {
            if (n0v[p] >= 0) {
                float x0 = fmaxf(mv[p].x + q0v[p].x + q1v[p].x + bv.x, 0.f);
                float x1 = fmaxf(mv[p].y + q0v[p].y + q1v[p].y + bv.y, 0.f);
                float x2 = fmaxf(mv[p].z + q0v[p].z + q1v[p].z + bv.z, 0.f);
                float x3 = fmaxf(mv[p].w + q0v[p].w + q1v[p].w + bv.w, 0.f);
                float* dst = &g_MS[(size_t)n0v[p] * MSGW + sub * 4];
                asm volatile("red.global.add.v4.f32 [%0], {%1,%2,%3,%4};"
                             :: "l"(dst), "f"(x0), "f"(x1), "f"(x2), "f"(x3)
                             : "memory");
            }
        }
    }
}

// ---------------------------------------------------------------------------
// K3 (HMMA, unchanged): out = relu(Q[:,64:192] + MS@Wn1 + bn).
// ---------------------------------------------------------------------------
__global__ __launch_bounds__(256, 4) void k_nodes(const float* __restrict__ Wn,
                                                  const float* __restrict__ bn,
                                                  float* __restrict__ out,
                                                  int N) {
    __shared__ __nv_bfloat16 sMSHi[64 * 40];
    __shared__ __nv_bfloat16 sMSLo[64 * 40];
    __shared__ __nv_bfloat16 sW1Hi[32 * 136];
    __shared__ __nv_bfloat16 sW1Lo[32 * 136];
    __shared__ float sBn[128];

    int t  = threadIdx.x;
    int m0 = blockIdx.x * 64;
    int wid = t >> 5, lane = t & 31;
    int warp_m = wid & 3, warp_n = wid >> 2;

#pragma unroll
    for (int id = t; id < 32 * 128; id += 256) {
        int k = id >> 7, c2 = id & 127;
        float v = Wn[(size_t)(FN + k) * FN + c2];
        __nv_bfloat16 h = __float2bfloat16(v);
        sW1Hi[k * 136 + c2] = h;
        sW1Lo[k * 136 + c2] = __float2bfloat16(v - __bfloat162float(h));
    }
    {
        int row = t >> 2, c0 = (t & 3) * 8;
        int n = m0 + row;
#pragma unroll
        for (int j = 0; j < 2; j++) {
            float4 v = (n < N)
                ? *(const float4*)&g_MS[(size_t)n * MSGW + c0 + 4 * j]
                : make_float4(0.f, 0.f, 0.f, 0.f);
            __nv_bfloat162 h0 = bf2_hi(v.x, v.y), h1 = bf2_hi(v.z, v.w);
            *(__nv_bfloat162*)&sMSHi[row * 40 + c0 + 4 * j]     = h0;
            *(__nv_bfloat162*)&sMSHi[row * 40 + c0 + 4 * j + 2] = h1;
            *(__nv_bfloat162*)&sMSLo[row * 40 + c0 + 4 * j]     = bf2_lo(v.x, v.y, h0);
            *(__nv_bfloat162*)&sMSLo[row * 40 + c0 + 4 * j + 2] = bf2_lo(v.z, v.w, h1);
        }
    }
    if (t < 128) sBn[t] = bn[t];
    __syncthreads();

    uint32_t aOff = (uint32_t)((warp_m * 16 + (lane & 15)) * 80 + (lane >> 4) * 16);
    uint32_t aHiB = sptr(sMSHi) + aOff;
    uint32_t aLoB = sptr(sMSLo) + aOff;
    uint32_t wRow = (uint32_t)((lane & 7) + 8 * ((lane >> 3) & 1));
    uint32_t wOff = wRow * 272 + (uint32_t)(warp_n * 64 + 8 * (lane >> 4)) * 2;
    uint32_t wHiB = sptr(sW1Hi) + wOff;
    uint32_t wLoB = sptr(sW1Lo) + wOff;

    float c[8][4];
#pragma unroll
    for (int nt = 0; nt < 8; nt++)
#pragma unroll
        for (int i = 0; i < 4; i++) c[nt][i] = 0.f;

#pragma unroll
    for (int ks = 0; ks < 2; ks++) {
        uint32_t ah[4], al[4];
        ldsm_x4(ah, aHiB + ks * 32);
        ldsm_x4(al, aLoB + ks * 32);
#pragma unroll
        for (int j = 0; j < 4; j++) {
            uint32_t bh[4], bl[4];
            ldsm_x4t(bh, wHiB + ks * 4352 + j * 32);
            ldsm_x4t(bl, wLoB + ks * 4352 + j * 32);
            mma16816(c[2 * j],     ah, bh[0], bh[1]);
            mma16816(c[2 * j],     al, bh[0], bh[1]);
            mma16816(c[2 * j],     ah, bl[0], bl[1]);
            mma16816(c[2 * j + 1], ah, bh[2], bh[3]);
            mma16816(c[2 * j + 1], al, bh[2], bh[3]);
            mma16816(c[2 * j + 1], ah, bl[2], bl[3]);
        }
    }

    int g = lane >> 2, tg = lane & 3;
#pragma unroll
    for (int nt = 0; nt < 8; nt++) {
        int col = warp_n * 64 + 8 * nt + 2 * tg;
        float2 b = *(const float2*)&sBn[col];
#pragma unroll
        for (int half = 0; half < 2; half++) {
            int row = m0 + warp_m * 16 + g + 8 * half;
            if (row < N) {
                float2 q = *(const float2*)&g_Q[(size_t)row * QW + 64 + col];
                float2 o;
                o.x = fmaxf(c[nt][2 * half]     + q.x + b.x, 0.f);
                o.y = fmaxf(c[nt][2 * half + 1] + q.y + b.y, 0.f);
                *(float2*)&out[(size_t)row * FN + col] = o;
            }
        }
    }
}

// ---------------------------------------------------------------------------
extern "C" void kernel_launch(void* const* d_in, const int* in_sizes, int n_in,
                              void* d_out, int out_size) {
    const float* nf  = (const float*)d_in[0];
    const void*  idx = d_in[1];
    const float* ef  = (const float*)d_in[2];
    const float* We  = (const float*)d_in[3];
    const float* be  = (const float*)d_in[4];
    const float* Wn  = (const float*)d_in[5];
    const float* bn  = (const float*)d_in[6];
    float* out = (float*)d_out;

    int N = in_sizes[0] / FN;
    int E = in_sizes[2] / FE;

    static int smem_set = 0;
    if (!smem_set) {
        cudaFuncSetAttribute(k_gemm1, cudaFuncAttributeMaxDynamicSharedMemorySize,
                             G1_SMEM);
        smem_set = 1;
    }

    int zb = (N * MSGW / 4 + 255) / 256;
    int wb = (128 * 192 + 255) / 256;
    k_prep<<<1 + zb + wb, 256>>>((const unsigned*)idx, We, Wn, E, N, zb);
    k_gemm1<<<(N + 63) / 64, 256, G1_SMEM>>>(nf, N);
    k_edges<<<(E + BE - 1) / BE, 256>>>(idx, ef, We, be, E);
    k_nodes<<<(N + 63) / 64, 256>>>(Wn, bn, out, N);
}